// round 11
// baseline (speedup 1.0000x reference)
#include <cuda_runtime.h>
#include <cuda_fp16.h>
#include <cstdint>
#include <cstddef>

#define D_MODEL 1024
#define SEQ     2048
#define BATCH   2
#define NHEAD   16
#define HDIM    64
#define MTOT    (BATCH * SEQ)          // 4096 rows

// ---------------------------------------------------------------------------
// Scratch (no cudaMalloc allowed) — fp16
// ---------------------------------------------------------------------------
__device__ __half g_xh[MTOT * D_MODEL];
__device__ __half g_xl[MTOT * D_MODEL];
__device__ __half g_wh[4 * D_MODEL * D_MODEL];   // Wq|Wk|Wv|Wo rows contiguous
__device__ __half g_qh[MTOT * D_MODEL];
__device__ __half g_ql[MTOT * D_MODEL];
__device__ __half g_kh[MTOT * D_MODEL];
__device__ __half g_vh[MTOT * D_MODEL];
__device__ __half g_oh[MTOT * D_MODEL];
__device__ __half g_ol[MTOT * D_MODEL];

// ---------------------------------------------------------------------------
// PTX helpers (sm_100-safe)
// ---------------------------------------------------------------------------
__device__ __forceinline__ uint32_t smem_u32(const void* p) {
    uint32_t a;
    asm("{ .reg .u64 t; cvta.to.shared.u64 t, %1; cvt.u32.u64 %0, t; }" : "=r"(a) : "l"(p));
    return a;
}
#define CP16(dst, src) \
    asm volatile("cp.async.cg.shared.global [%0], [%1], 16;" :: "r"(dst), "l"(src))
#define CP_COMMIT() asm volatile("cp.async.commit_group;" ::: "memory")
#define CP_WAIT(n)  asm volatile("cp.async.wait_group %0;" :: "n"(n) : "memory")

#define LDSM4(r0, r1, r2, r3, addr) \
    asm volatile("ldmatrix.sync.aligned.m8n8.x4.shared.b16 {%0,%1,%2,%3}, [%4];" \
                 : "=r"(r0), "=r"(r1), "=r"(r2), "=r"(r3) : "r"(addr))
#define LDSM4T(r0, r1, r2, r3, addr) \
    asm volatile("ldmatrix.sync.aligned.m8n8.x4.trans.shared.b16 {%0,%1,%2,%3}, [%4];" \
                 : "=r"(r0), "=r"(r1), "=r"(r2), "=r"(r3) : "r"(addr))

#define MMA_F16(d, a, b0, b1) \
    asm volatile("mma.sync.aligned.m16n8k16.row.col.f32.f16.f16.f32 " \
                 "{%0,%1,%2,%3}, {%4,%5,%6,%7}, {%8,%9}, {%0,%1,%2,%3};" \
                 : "+f"((d)[0]), "+f"((d)[1]), "+f"((d)[2]), "+f"((d)[3]) \
                 : "r"((a)[0]), "r"((a)[1]), "r"((a)[2]), "r"((a)[3]), \
                   "r"(b0), "r"(b1))

// exact fp16 hi + residual split of two fp32 values
__device__ __forceinline__ void split2h(float a, float b, uint32_t& hi, uint32_t& lo) {
    __half2 h = __floats2half2_rn(a, b);
    float ra = a - __half2float(__low2half(h));
    float rb = b - __half2float(__high2half(h));
    __half2 l = __floats2half2_rn(ra, rb);
    hi = *(uint32_t*)&h;
    lo = *(uint32_t*)&l;
}
__device__ __forceinline__ uint32_t pack2h(float a, float b) {
    __half2 h = __floats2half2_rn(a, b);
    return *(uint32_t*)&h;
}

// ---------------------------------------------------------------------------
// Merged preprocessing, 4 strided float4s per thread (MLP=4).
// ---------------------------------------------------------------------------
#define N4X (MTOT * D_MODEL / 4)       // 1048576
#define N4W (D_MODEL * D_MODEL / 4)    // 262144 = 1<<18
#define WN  (D_MODEL * D_MODEL)
#define NPREP (N4X + 4 * N4W)          // 2097152
#define PREP_BLOCKS (NPREP / (256 * 4))  // 2048

__global__ __launch_bounds__(256) void prep_kernel(
    const float* __restrict__ x,
    const float* __restrict__ Wq, const float* __restrict__ Wk,
    const float* __restrict__ Wv, const float* __restrict__ Wo,
    __half* __restrict__ xh, __half* __restrict__ xl, __half* __restrict__ wh)
{
    const int stride = PREP_BLOCKS * 256;
#pragma unroll
    for (int rep = 0; rep < 4; rep++) {
        int i = blockIdx.x * 256 + threadIdx.x + rep * stride;
        if (i < N4X) {
            float4 v = ((const float4*)x)[i];
            uint32_t h0, l0, h1, l1;
            split2h(v.x, v.y, h0, l0);
            split2h(v.z, v.w, h1, l1);
            ((uint32_t*)xh)[2 * i] = h0;  ((uint32_t*)xh)[2 * i + 1] = h1;
            ((uint32_t*)xl)[2 * i] = l0;  ((uint32_t*)xl)[2 * i + 1] = l1;
        } else {
            int t = i - N4X;
            int j = t >> 18;
            int w = t & (N4W - 1);
            const float* src = (j == 0) ? Wq : (j == 1) ? Wk : (j == 2) ? Wv : Wo;
            float4 v = ((const float4*)src)[w];
            __half2* dst = (__half2*)(wh + (size_t)j * WN);
            dst[2 * w] = __floats2half2_rn(v.x, v.y);
            dst[2 * w + 1] = __floats2half2_rn(v.z, v.w);
        }
    }
}

// ---------------------------------------------------------------------------
// GEMM core: 128x128 C tile, BK=64 chunks (32 chunks: hi half then lo half),
// 3-stage cp.async ring, ONE __syncthreads per chunk.
// All per-thread addresses hoisted out of the mainloop (32-bit offsets).
// ---------------------------------------------------------------------------
#define GK 1024
#define GLD 72                          // row stride in fp16 (144 B, conflict-free)
#define GTB  (128 * GLD * 2)            // 18432 B per matrix tile
#define GSTB (2 * GTB)                  // 36864 B per stage (A + B)
#define GEMM_SMEM (3 * GSTB)            // 110592 B -> 2 CTAs/SM
#define NCH 32

struct GemmCore {
    uint32_t smb;
    int lane, wr, wc;
    uint32_t dstA[4];                   // smem dst byte offsets (A; W = +GTB)
    uint32_t offA[4], offW[4];          // gmem element offsets (32-bit)
    uint32_t aRow[4], bRow[2];          // LDSM smem row byte offsets
    float acc[4][4][4];

    __device__ __forceinline__ void init(uint32_t smb_, int tid, int bm, int bn) {
        smb = smb_;
        const int wid = tid >> 5;
        lane = tid & 31;
        wr = (wid & 1) * 64; wc = (wid >> 1) * 32;
#pragma unroll
        for (int it = 0; it < 4; it++) {
            int idx = tid + it * 256;
            int r = idx >> 3, u = idx & 7;
            dstA[it] = (uint32_t)(r * GLD) * 2 + u * 16;
            offA[it] = (uint32_t)(bm + r) * GK + u * 8;
            offW[it] = (uint32_t)(bn + r) * GK + u * 8;
        }
#pragma unroll
        for (int mt = 0; mt < 4; mt++)
            aRow[mt] = (uint32_t)((wr + mt * 16 + (lane & 15)) * GLD) * 2 + (lane >> 4) * 16;
#pragma unroll
        for (int ng = 0; ng < 2; ng++)
            bRow[ng] = GTB + (uint32_t)((wc + ng * 16 + (lane & 15)) * GLD) * 2 + (lane >> 4) * 16;
#pragma unroll
        for (int mt = 0; mt < 4; mt++)
#pragma unroll
            for (int j = 0; j < 4; j++)
#pragma unroll
                for (int r = 0; r < 4; r++) acc[mt][j][r] = 0.0f;
    }
    __device__ __forceinline__ void load_chunk(
        const __half* __restrict__ Ahi, const __half* __restrict__ Alo,
        const __half* __restrict__ W, int c, int stg) {
        const __half* Ap = ((c >= 16) ? Alo : Ahi) + (c & 15) * 64;
        const __half* Wp = W + (c & 15) * 64;
        const uint32_t sa = smb + stg * GSTB;
#pragma unroll
        for (int it = 0; it < 4; it++)
            CP16(sa + dstA[it], Ap + offA[it]);
#pragma unroll
        for (int it = 0; it < 4; it++)
            CP16(sa + GTB + dstA[it], Wp + offW[it]);
    }
    __device__ __forceinline__ void compute(int stg) {
        const uint32_t sa = smb + stg * GSTB;
#pragma unroll
        for (int ks = 0; ks < 4; ks++) {
            const uint32_t colb = ks * 32;
            uint32_t a[4][4], b[2][4];
#pragma unroll
            for (int mt = 0; mt < 4; mt++)
                LDSM4(a[mt][0], a[mt][1], a[mt][2], a[mt][3], sa + aRow[mt] + colb);
#pragma unroll
            for (int ng = 0; ng < 2; ng++)
                LDSM4(b[ng][0], b[ng][1], b[ng][2], b[ng][3], sa + bRow[ng] + colb);
#pragma unroll
            for (int mt = 0; mt < 4; mt++)
#pragma unroll
                for (int j = 0; j < 4; j++)
                    MMA_F16(acc[mt][j], a[mt], b[j >> 1][j & 1], b[j >> 1][(j & 1) + 2]);
        }
    }
    __device__ __forceinline__ void run(
        const __half* __restrict__ Ahi, const __half* __restrict__ Alo,
        const __half* __restrict__ W) {
        load_chunk(Ahi, Alo, W, 0, 0); CP_COMMIT();
        load_chunk(Ahi, Alo, W, 1, 1); CP_COMMIT();
        for (int c = 0; c < NCH; c++) {
            CP_WAIT(1);
            __syncthreads();
            if (c + 2 < NCH) load_chunk(Ahi, Alo, W, c + 2, (c + 2) % 3);
            CP_COMMIT();
            compute(c % 3);
        }
    }
};

// ---------------------------------------------------------------------------
// Fused QKV GEMM: N=3072 over contiguous Wq|Wk|Wv. bn>>10 selects output:
// 0 -> Q (fp16 hi+lo), 1 -> K (hi), 2 -> V (hi).
// ---------------------------------------------------------------------------
__global__ __launch_bounds__(256, 2) void gemm_qkv(
    const __half* __restrict__ Ahi, const __half* __restrict__ Alo,
    const __half* __restrict__ W,
    const float* __restrict__ bq, const float* __restrict__ bk,
    const float* __restrict__ bv,
    __half* __restrict__ Qh, __half* __restrict__ Ql,
    __half* __restrict__ Kh, __half* __restrict__ Vh)
{
    extern __shared__ __align__(128) char smg[];
    const int bn = blockIdx.x * 128;            // 0..2944
    const int bm = blockIdx.y * 128;
    GemmCore g;
    g.init(smem_u32(smg), threadIdx.x, bm, bn);
    g.run(Ahi, Alo, W);

    const int bh = bn >> 10;                    // 0:Q 1:K 2:V
    const int cb = bn & 1023;
    const float* bias = (bh == 0) ? bq : (bh == 1) ? bk : bv;
    const int rq = g.lane >> 2;
    const int cq = (g.lane & 3) * 2;
#pragma unroll
    for (int mt = 0; mt < 4; mt++) {
#pragma unroll
        for (int j = 0; j < 4; j++) {
            const int col = cb + g.wc + j * 8 + cq;
            const float b0 = bias[col], b1 = bias[col + 1];
            const int row0 = bm + g.wr + mt * 16 + rq;
            float v0 = g.acc[mt][j][0] + b0, v1 = g.acc[mt][j][1] + b1;
            float v2 = g.acc[mt][j][2] + b0, v3 = g.acc[mt][j][3] + b1;
            if (bh == 0) {
                uint32_t h01, l01;
                split2h(v0, v1, h01, l01);
                *(uint32_t*)(Qh + (size_t)row0 * D_MODEL + col) = h01;
                *(uint32_t*)(Ql + (size_t)row0 * D_MODEL + col) = l01;
                split2h(v2, v3, h01, l01);
                *(uint32_t*)(Qh + (size_t)(row0 + 8) * D_MODEL + col) = h01;
                *(uint32_t*)(Ql + (size_t)(row0 + 8) * D_MODEL + col) = l01;
            } else {
                __half* dst = (bh == 1) ? Kh : Vh;
                *(__half2*)(dst + (size_t)row0 * D_MODEL + col) = __floats2half2_rn(v0, v1);
                *(__half2*)(dst + (size_t)(row0 + 8) * D_MODEL + col) = __floats2half2_rn(v2, v3);
            }
        }
    }
}

// ---------------------------------------------------------------------------
// Output projection GEMM: fp32 out + bias, N=1024.
// ---------------------------------------------------------------------------
__global__ __launch_bounds__(256, 2) void gemm_out(
    const __half* __restrict__ Ahi, const __half* __restrict__ Alo,
    const __half* __restrict__ W,
    const float* __restrict__ bias, float* __restrict__ C)
{
    extern __shared__ __align__(128) char smg[];
    const int bn = blockIdx.x * 128;
    const int bm = blockIdx.y * 128;
    GemmCore g;
    g.init(smem_u32(smg), threadIdx.x, bm, bn);
    g.run(Ahi, Alo, W);

    const int rq = g.lane >> 2;
    const int cq = (g.lane & 3) * 2;
#pragma unroll
    for (int mt = 0; mt < 4; mt++) {
#pragma unroll
        for (int j = 0; j < 4; j++) {
            const int col = bn + g.wc + j * 8 + cq;
            const float b0 = bias[col], b1 = bias[col + 1];
            const int row0 = bm + g.wr + mt * 16 + rq;
            *(float2*)(C + (size_t)row0 * D_MODEL + col) =
                make_float2(g.acc[mt][j][0] + b0, g.acc[mt][j][1] + b1);
            *(float2*)(C + (size_t)(row0 + 8) * D_MODEL + col) =
                make_float2(g.acc[mt][j][2] + b0, g.acc[mt][j][3] + b1);
        }
    }
}

// ---------------------------------------------------------------------------
// Flash attention, fp16 mma.sync, causal. Paired Q tiles (balanced wave).
// S = (qh+ql) K^T (2-term);  PV = P V with single-fp16 P (1 term).
// 3-stage KV ring, 2 CTAs/SM.
// ---------------------------------------------------------------------------
#define ALD 72
#define AQ_B  (128 * ALD * 2)          // 18432 B per Q matrix
#define AM_B  (64 * ALD * 2)           // 9216 B per K/V matrix
#define AST_B (2 * AM_B)               // stage: Kh,Vh = 18432 B
#define ATTN_SMEM (2 * AQ_B + 3 * AST_B)   // 92160 B -> 2 CTAs/SM

#define SCL 0.18033688f                // 0.125 * log2(e)

__global__ __launch_bounds__(256, 2) void attn_mma(
    const __half* __restrict__ Qhi, const __half* __restrict__ Qlo,
    const __half* __restrict__ Kh, const __half* __restrict__ Vh,
    __half* __restrict__ Ohi, __half* __restrict__ Olo)
{
    extern __shared__ __align__(128) char smc[];
    const uint32_t smb = smem_u32(smc);
    const int tid = threadIdx.x;
    const int wid = tid >> 5;
    const int lane = tid & 31;
    const int bx = blockIdx.x;
    const int h = blockIdx.y, b = blockIdx.z;
    const size_t rc0 = (size_t)b * SEQ * D_MODEL + h * HDIM;

    const int wr = wid * 16;
    const uint32_t lrow = lane & 15;
    const uint32_t lc16 = (lane >> 4) * 16;

    auto load_q = [&](int q0) {
#pragma unroll
        for (int it = 0; it < 8; it++) {
            int t = tid + it * 256;
            const __half* src = (t < 1024) ? Qhi : Qlo;
            uint32_t moff = (t < 1024) ? 0u : (uint32_t)AQ_B;
            int idx = t & 1023, r = idx >> 3, u = idx & 7;
            CP16(smb + moff + (uint32_t)(r * ALD + u * 8) * 2,
                 src + rc0 + (size_t)(q0 + r) * D_MODEL + u * 8);
        }
    };
    auto load_kv = [&](int kt, int stg) {
        const uint32_t sb = smb + 2 * AQ_B + stg * AST_B;
#pragma unroll
        for (int it = 0; it < 4; it++) {
            int t = tid + it * 256;
            int mtx = t >> 9;                       // 0:Kh 1:Vh
            int idx = t & 511, r = idx >> 3, u = idx & 7;
            const __half* src = (mtx == 0) ? Kh : Vh;
            CP16(sb + mtx * AM_B + (uint32_t)(r * ALD + u * 8) * 2,
                 src + rc0 + (size_t)(kt * 64 + r) * D_MODEL + u * 8);
        }
    };

    for (int half = 0; half < 2; half++) {
        const int qt = half ? (7 - bx) : (8 + bx);
        const int q0 = qt * 128;
        const int ktEnd = 2 * qt + 2;

        float o[8][4];
#pragma unroll
        for (int nt = 0; nt < 8; nt++)
#pragma unroll
            for (int c = 0; c < 4; c++) o[nt][c] = 0.0f;
        float m0 = -1e30f, m1 = -1e30f, l0 = 0.0f, l1 = 0.0f;
        uint32_t qh[4][4];

        load_q(q0);
        load_kv(0, 0);
        CP_COMMIT();
        if (1 < ktEnd) load_kv(1, 1);
        CP_COMMIT();

        for (int kt = 0; kt < ktEnd; kt++) {
            CP_WAIT(1);
            __syncthreads();
            if (kt + 2 < ktEnd) load_kv(kt + 2, (kt + 2) % 3);
            CP_COMMIT();

            if (kt == 0) {
#pragma unroll
                for (int ks = 0; ks < 4; ks++) {
                    uint32_t a1 = smb + (uint32_t)((wr + lrow) * ALD) * 2 + ks * 32 + lc16;
                    LDSM4(qh[ks][0], qh[ks][1], qh[ks][2], qh[ks][3], a1);
                }
            }

            const uint32_t sb = smb + 2 * AQ_B + (kt % 3) * AST_B;

            // ---- S = (qh+ql) K^T  (ql reloaded from smem) ----
            float s[8][4];
#pragma unroll
            for (int nt = 0; nt < 8; nt++)
#pragma unroll
                for (int c = 0; c < 4; c++) s[nt][c] = 0.0f;

#pragma unroll
            for (int ks = 0; ks < 4; ks++) {
                uint32_t kf[4][4];
#pragma unroll
                for (int ng = 0; ng < 4; ng++) {
                    uint32_t a1 = sb + (uint32_t)((ng * 16 + lrow) * ALD) * 2 + ks * 32 + lc16;
                    LDSM4(kf[ng][0], kf[ng][1], kf[ng][2], kf[ng][3], a1);
                }
                uint32_t ql[4];
                uint32_t aq = smb + AQ_B + (uint32_t)((wr + lrow) * ALD) * 2 + ks * 32 + lc16;
                LDSM4(ql[0], ql[1], ql[2], ql[3], aq);
#pragma unroll
                for (int nt = 0; nt < 8; nt++) {
                    MMA_F16(s[nt], qh[ks], kf[nt >> 1][nt & 1], kf[nt >> 1][(nt & 1) + 2]);
                    MMA_F16(s[nt], ql, kf[nt >> 1][nt & 1], kf[nt >> 1][(nt & 1) + 2]);
                }
            }

#pragma unroll
            for (int nt = 0; nt < 8; nt++)
#pragma unroll
                for (int c = 0; c < 4; c++) s[nt][c] *= SCL;   // log2-domain

            // ---- causal mask (diagonal tiles only) ----
            if (kt * 64 + 63 > q0 + wr) {
                const int r0 = q0 + wr + (lane >> 2);
#pragma unroll
                for (int nt = 0; nt < 8; nt++) {
                    const int c0 = kt * 64 + nt * 8 + 2 * (lane & 3);
                    if (c0 > r0)         s[nt][0] = -1e30f;
                    if (c0 + 1 > r0)     s[nt][1] = -1e30f;
                    if (c0 > r0 + 8)     s[nt][2] = -1e30f;
                    if (c0 + 1 > r0 + 8) s[nt][3] = -1e30f;
                }
            }

            // ---- online softmax (base-2, quad shuffles) ----
            float mx0 = -1e30f, mx1 = -1e30f;
#pragma unroll
            for (int nt = 0; nt < 8; nt++) {
                mx0 = fmaxf(mx0, fmaxf(s[nt][0], s[nt][1]));
                mx1 = fmaxf(mx1, fmaxf(s[nt][2], s[nt][3]));
            }
            mx0 = fmaxf(mx0, __shfl_xor_sync(0xffffffffu, mx0, 1));
            mx0 = fmaxf(mx0, __shfl_xor_sync(0xffffffffu, mx0, 2));
            mx1 = fmaxf(mx1, __shfl_xor_sync(0xffffffffu, mx1, 1));
            mx1 = fmaxf(mx1, __shfl_xor_sync(0xffffffffu, mx1, 2));
            const float n0 = fmaxf(m0, mx0), n1 = fmaxf(m1, mx1);
            const float cr0 = exp2f(m0 - n0), cr1 = exp2f(m1 - n1);
            m0 = n0; m1 = n1;
            float sum0 = 0.0f, sum1 = 0.0f;
#pragma unroll
            for (int nt = 0; nt < 8; nt++) {
                s[nt][0] = exp2f(s[nt][0] - n0); sum0 += s[nt][0];
                s[nt][1] = exp2f(s[nt][1] - n0); sum0 += s[nt][1];
                s[nt][2] = exp2f(s[nt][2] - n1); sum1 += s[nt][2];
                s[nt][3] = exp2f(s[nt][3] - n1); sum1 += s[nt][3];
            }
            sum0 += __shfl_xor_sync(0xffffffffu, sum0, 1);
            sum0 += __shfl_xor_sync(0xffffffffu, sum0, 2);
            sum1 += __shfl_xor_sync(0xffffffffu, sum1, 1);
            sum1 += __shfl_xor_sync(0xffffffffu, sum1, 2);
            l0 = l0 * cr0 + sum0;
            l1 = l1 * cr1 + sum1;
#pragma unroll
            for (int nt = 0; nt < 8; nt++) {
                o[nt][0] *= cr0; o[nt][1] *= cr0;
                o[nt][2] *= cr1; o[nt][3] *= cr1;
            }

            // ---- P fragments: single fp16 ----
            uint32_t ph[4][4];
#pragma unroll
            for (int ks = 0; ks < 4; ks++) {
                ph[ks][0] = pack2h(s[2 * ks][0], s[2 * ks][1]);
                ph[ks][1] = pack2h(s[2 * ks][2], s[2 * ks][3]);
                ph[ks][2] = pack2h(s[2 * ks + 1][0], s[2 * ks + 1][1]);
                ph[ks][3] = pack2h(s[2 * ks + 1][2], s[2 * ks + 1][3]);
            }

            // ---- O += P V (1 term) ----
#pragma unroll
            for (int ks = 0; ks < 4; ks++) {
                uint32_t vh[4][4];
#pragma unroll
                for (int ng = 0; ng < 4; ng++) {
                    uint32_t a1 = sb + AM_B + (uint32_t)((ks * 16 + lrow) * ALD) * 2 + ng * 32 + lc16;
                    LDSM4T(vh[ng][0], vh[ng][1], vh[ng][2], vh[ng][3], a1);
                }
#pragma unroll
                for (int nt = 0; nt < 8; nt++)
                    MMA_F16(o[nt], ph[ks], vh[nt >> 1][(nt & 1) * 2], vh[nt >> 1][(nt & 1) * 2 + 1]);
            }
        }

        // ---- epilogue: normalize, exact-split to fp16 hi/lo ----
        const float i0 = 1.0f / l0, i1 = 1.0f / l1;
        const size_t r0 = (size_t)(b * SEQ + q0 + wr + (lane >> 2));
        const int colb = h * HDIM + 2 * (lane & 3);
#pragma unroll
        for (int nt = 0; nt < 8; nt++) {
            const int col = colb + nt * 8;
            uint32_t h01, l01;
            split2h(o[nt][0] * i0, o[nt][1] * i0, h01, l01);
            *(uint32_t*)(Ohi + r0 * D_MODEL + col) = h01;
            *(uint32_t*)(Olo + r0 * D_MODEL + col) = l01;
            split2h(o[nt][2] * i1, o[nt][3] * i1, h01, l01);
            *(uint32_t*)(Ohi + (r0 + 8) * D_MODEL + col) = h01;
            *(uint32_t*)(Olo + (r0 + 8) * D_MODEL + col) = l01;
        }

        // drain before next tile reuses Q/KV smem
        CP_WAIT(0);
        __syncthreads();
    }
}

// ---------------------------------------------------------------------------
// Launch
// ---------------------------------------------------------------------------
extern "C" void kernel_launch(void* const* d_in, const int* in_sizes, int n_in,
                              void* d_out, int out_size)
{
    (void)in_sizes; (void)n_in; (void)out_size;
    const float* x  = (const float*)d_in[0];
    const float* Wq = (const float*)d_in[1];
    const float* bq = (const float*)d_in[2];
    const float* Wk = (const float*)d_in[3];
    const float* bk = (const float*)d_in[4];
    const float* Wv = (const float*)d_in[5];
    const float* bv = (const float*)d_in[6];
    const float* Wo = (const float*)d_in[7];
    const float* bo = (const float*)d_in[8];
    float* out = (float*)d_out;

    __half *xh, *xl, *wh, *qh, *ql, *kh, *vh, *oh, *ol;
    cudaGetSymbolAddress((void**)&xh, g_xh);
    cudaGetSymbolAddress((void**)&xl, g_xl);
    cudaGetSymbolAddress((void**)&wh, g_wh);
    cudaGetSymbolAddress((void**)&qh, g_qh);
    cudaGetSymbolAddress((void**)&ql, g_ql);
    cudaGetSymbolAddress((void**)&kh, g_kh);
    cudaGetSymbolAddress((void**)&vh, g_vh);
    cudaGetSymbolAddress((void**)&oh, g_oh);
    cudaGetSymbolAddress((void**)&ol, g_ol);

    cudaFuncSetAttribute(attn_mma,
                         cudaFuncAttributeMaxDynamicSharedMemorySize, ATTN_SMEM);
    cudaFuncSetAttribute(gemm_qkv,
                         cudaFuncAttributeMaxDynamicSharedMemorySize, GEMM_SMEM);
    cudaFuncSetAttribute(gemm_out,
                         cudaFuncAttributeMaxDynamicSharedMemorySize, GEMM_SMEM);

    prep_kernel<<<PREP_BLOCKS, 256>>>(x, Wq, Wk, Wv, Wo, xh, xl, wh);

    dim3 gQKV(3 * D_MODEL / 128, MTOT / 128);   // (24, 32)
    gemm_qkv<<<gQKV, 256, GEMM_SMEM>>>(xh, xl, wh, bq, bk, bv, qh, ql, kh, vh);

    dim3 gAttn(SEQ / 256, NHEAD, BATCH);        // (8, 16, 2) - paired tiles
    attn_mma<<<gAttn, 256, ATTN_SMEM>>>(qh, ql, kh, vh, oh, ol);

    dim3 gOut(D_MODEL / 128, MTOT / 128);       // (8, 32)
    gemm_out<<<gOut, 256, GEMM_SMEM>>>(oh, ol, wh + (size_t)3 * WN, bo, out);
}

// round 12
// speedup vs baseline: 1.6646x; 1.6646x over previous
#include <cuda_runtime.h>
#include <cuda_fp16.h>
#include <cstdint>
#include <cstddef>

#define D_MODEL 1024
#define SEQ     2048
#define BATCH   2
#define NHEAD   16
#define HDIM    64
#define MTOT    (BATCH * SEQ)          // 4096 rows

// ---------------------------------------------------------------------------
// Scratch (no cudaMalloc allowed) — all single fp16
// ---------------------------------------------------------------------------
__device__ __half g_xh[MTOT * D_MODEL];
__device__ __half g_wh[4 * D_MODEL * D_MODEL];   // Wq|Wk|Wv|Wo rows contiguous
__device__ __half g_qh[MTOT * D_MODEL];
__device__ __half g_kh[MTOT * D_MODEL];
__device__ __half g_vh[MTOT * D_MODEL];
__device__ __half g_oh[MTOT * D_MODEL];

// ---------------------------------------------------------------------------
// PTX helpers (sm_100-safe)
// ---------------------------------------------------------------------------
__device__ __forceinline__ uint32_t smem_u32(const void* p) {
    uint32_t a;
    asm("{ .reg .u64 t; cvta.to.shared.u64 t, %1; cvt.u32.u64 %0, t; }" : "=r"(a) : "l"(p));
    return a;
}
#define CP16(dst, src) \
    asm volatile("cp.async.cg.shared.global [%0], [%1], 16;" :: "r"(dst), "l"(src))
#define CP_COMMIT() asm volatile("cp.async.commit_group;" ::: "memory")
#define CP_WAIT(n)  asm volatile("cp.async.wait_group %0;" :: "n"(n) : "memory")

#define LDSM4(r0, r1, r2, r3, addr) \
    asm volatile("ldmatrix.sync.aligned.m8n8.x4.shared.b16 {%0,%1,%2,%3}, [%4];" \
                 : "=r"(r0), "=r"(r1), "=r"(r2), "=r"(r3) : "r"(addr))
#define LDSM4T(r0, r1, r2, r3, addr) \
    asm volatile("ldmatrix.sync.aligned.m8n8.x4.trans.shared.b16 {%0,%1,%2,%3}, [%4];" \
                 : "=r"(r0), "=r"(r1), "=r"(r2), "=r"(r3) : "r"(addr))

#define MMA_F16(d, a, b0, b1) \
    asm volatile("mma.sync.aligned.m16n8k16.row.col.f32.f16.f16.f32 " \
                 "{%0,%1,%2,%3}, {%4,%5,%6,%7}, {%8,%9}, {%0,%1,%2,%3};" \
                 : "+f"((d)[0]), "+f"((d)[1]), "+f"((d)[2]), "+f"((d)[3]) \
                 : "r"((a)[0]), "r"((a)[1]), "r"((a)[2]), "r"((a)[3]), \
                   "r"(b0), "r"(b1))

__device__ __forceinline__ uint32_t pack2h(float a, float b) {
    __half2 h = __floats2half2_rn(a, b);
    return *(uint32_t*)&h;
}

// ---------------------------------------------------------------------------
// Merged preprocessing: fp32 -> fp16 cvt of x and 4 weights. MLP=4.
// ---------------------------------------------------------------------------
#define N4X (MTOT * D_MODEL / 4)       // 1048576
#define N4W (D_MODEL * D_MODEL / 4)    // 262144 = 1<<18
#define WN  (D_MODEL * D_MODEL)
#define NPREP (N4X + 4 * N4W)          // 2097152
#define PREP_BLOCKS (NPREP / (256 * 4))  // 2048

__global__ __launch_bounds__(256) void prep_kernel(
    const float* __restrict__ x,
    const float* __restrict__ Wq, const float* __restrict__ Wk,
    const float* __restrict__ Wv, const float* __restrict__ Wo,
    __half* __restrict__ xh, __half* __restrict__ wh)
{
    const int stride = PREP_BLOCKS * 256;
#pragma unroll
    for (int rep = 0; rep < 4; rep++) {
        int i = blockIdx.x * 256 + threadIdx.x + rep * stride;
        const float* src;
        __half2* dst;
        int w;
        if (i < N4X) {
            src = x; dst = (__half2*)xh; w = i;
        } else {
            int t = i - N4X;
            int j = t >> 18;
            w = t & (N4W - 1);
            src = (j == 0) ? Wq : (j == 1) ? Wk : (j == 2) ? Wv : Wo;
            dst = (__half2*)(wh + (size_t)j * WN);
        }
        float4 v = ((const float4*)src)[w];
        dst[2 * w] = __floats2half2_rn(v.x, v.y);
        dst[2 * w + 1] = __floats2half2_rn(v.z, v.w);
    }
}

// ---------------------------------------------------------------------------
// GEMM core: 128x128 C tile, BK=64 chunks, K=1024 -> 16 chunks, single fp16 A.
// 3-stage cp.async ring, ONE __syncthreads per chunk. Hoisted addresses.
// ---------------------------------------------------------------------------
#define GK 1024
#define GLD 72                          // row stride in fp16 (144 B, conflict-free)
#define GTB  (128 * GLD * 2)            // 18432 B per matrix tile
#define GSTB (2 * GTB)                  // 36864 B per stage (A + B)
#define GEMM_SMEM (3 * GSTB)            // 110592 B -> 2 CTAs/SM
#define NCH 16

struct GemmCore {
    uint32_t smb;
    int lane, wr, wc;
    uint32_t dstA[4];                   // smem dst byte offsets (A; W = +GTB)
    uint32_t offA[4], offW[4];          // gmem element offsets (32-bit)
    uint32_t aRow[4], bRow[2];          // LDSM smem row byte offsets
    float acc[4][4][4];

    __device__ __forceinline__ void init(uint32_t smb_, int tid, int bm, int bn) {
        smb = smb_;
        const int wid = tid >> 5;
        lane = tid & 31;
        wr = (wid & 1) * 64; wc = (wid >> 1) * 32;
#pragma unroll
        for (int it = 0; it < 4; it++) {
            int idx = tid + it * 256;
            int r = idx >> 3, u = idx & 7;
            dstA[it] = (uint32_t)(r * GLD) * 2 + u * 16;
            offA[it] = (uint32_t)(bm + r) * GK + u * 8;
            offW[it] = (uint32_t)(bn + r) * GK + u * 8;
        }
#pragma unroll
        for (int mt = 0; mt < 4; mt++)
            aRow[mt] = (uint32_t)((wr + mt * 16 + (lane & 15)) * GLD) * 2 + (lane >> 4) * 16;
#pragma unroll
        for (int ng = 0; ng < 2; ng++)
            bRow[ng] = GTB + (uint32_t)((wc + ng * 16 + (lane & 15)) * GLD) * 2 + (lane >> 4) * 16;
#pragma unroll
        for (int mt = 0; mt < 4; mt++)
#pragma unroll
            for (int j = 0; j < 4; j++)
#pragma unroll
                for (int r = 0; r < 4; r++) acc[mt][j][r] = 0.0f;
    }
    __device__ __forceinline__ void load_chunk(
        const __half* __restrict__ A, const __half* __restrict__ W,
        int c, int stg) {
        const __half* Ap = A + c * 64;
        const __half* Wp = W + c * 64;
        const uint32_t sa = smb + stg * GSTB;
#pragma unroll
        for (int it = 0; it < 4; it++)
            CP16(sa + dstA[it], Ap + offA[it]);
#pragma unroll
        for (int it = 0; it < 4; it++)
            CP16(sa + GTB + dstA[it], Wp + offW[it]);
    }
    __device__ __forceinline__ void compute(int stg) {
        const uint32_t sa = smb + stg * GSTB;
#pragma unroll
        for (int ks = 0; ks < 4; ks++) {
            const uint32_t colb = ks * 32;
            uint32_t a[4][4], b[2][4];
#pragma unroll
            for (int mt = 0; mt < 4; mt++)
                LDSM4(a[mt][0], a[mt][1], a[mt][2], a[mt][3], sa + aRow[mt] + colb);
#pragma unroll
            for (int ng = 0; ng < 2; ng++)
                LDSM4(b[ng][0], b[ng][1], b[ng][2], b[ng][3], sa + bRow[ng] + colb);
#pragma unroll
            for (int mt = 0; mt < 4; mt++)
#pragma unroll
                for (int j = 0; j < 4; j++)
                    MMA_F16(acc[mt][j], a[mt], b[j >> 1][j & 1], b[j >> 1][(j & 1) + 2]);
        }
    }
    __device__ __forceinline__ void run(
        const __half* __restrict__ A, const __half* __restrict__ W) {
        load_chunk(A, W, 0, 0); CP_COMMIT();
        load_chunk(A, W, 1, 1); CP_COMMIT();
        for (int c = 0; c < NCH; c++) {
            CP_WAIT(1);
            __syncthreads();
            if (c + 2 < NCH) load_chunk(A, W, c + 2, (c + 2) % 3);
            CP_COMMIT();
            compute(c % 3);
        }
    }
};

// ---------------------------------------------------------------------------
// Fused QKV GEMM: N=3072 over contiguous Wq|Wk|Wv; bn>>10 selects Q/K/V dst.
// All outputs single fp16.
// ---------------------------------------------------------------------------
__global__ __launch_bounds__(256, 2) void gemm_qkv(
    const __half* __restrict__ A, const __half* __restrict__ W,
    const float* __restrict__ bq, const float* __restrict__ bk,
    const float* __restrict__ bv,
    __half* __restrict__ Qh, __half* __restrict__ Kh, __half* __restrict__ Vh)
{
    extern __shared__ __align__(128) char smg[];
    const int bn = blockIdx.x * 128;            // 0..2944
    const int bm = blockIdx.y * 128;
    GemmCore g;
    g.init(smem_u32(smg), threadIdx.x, bm, bn);
    g.run(A, W);

    const int bh = bn >> 10;                    // 0:Q 1:K 2:V
    const int cb = bn & 1023;
    const float* bias = (bh == 0) ? bq : (bh == 1) ? bk : bv;
    __half* dst = (bh == 0) ? Qh : (bh == 1) ? Kh : Vh;
    const int rq = g.lane >> 2;
    const int cq = (g.lane & 3) * 2;
#pragma unroll
    for (int mt = 0; mt < 4; mt++) {
#pragma unroll
        for (int j = 0; j < 4; j++) {
            const int col = cb + g.wc + j * 8 + cq;
            const float b0 = bias[col], b1 = bias[col + 1];
            const int row0 = bm + g.wr + mt * 16 + rq;
            *(__half2*)(dst + (size_t)row0 * D_MODEL + col) =
                __floats2half2_rn(g.acc[mt][j][0] + b0, g.acc[mt][j][1] + b1);
            *(__half2*)(dst + (size_t)(row0 + 8) * D_MODEL + col) =
                __floats2half2_rn(g.acc[mt][j][2] + b0, g.acc[mt][j][3] + b1);
        }
    }
}

// ---------------------------------------------------------------------------
// Output projection GEMM: fp32 out + bias, N=1024.
// ---------------------------------------------------------------------------
__global__ __launch_bounds__(256, 2) void gemm_out(
    const __half* __restrict__ A, const __half* __restrict__ W,
    const float* __restrict__ bias, float* __restrict__ C)
{
    extern __shared__ __align__(128) char smg[];
    const int bn = blockIdx.x * 128;
    const int bm = blockIdx.y * 128;
    GemmCore g;
    g.init(smem_u32(smg), threadIdx.x, bm, bn);
    g.run(A, W);

    const int rq = g.lane >> 2;
    const int cq = (g.lane & 3) * 2;
#pragma unroll
    for (int mt = 0; mt < 4; mt++) {
#pragma unroll
        for (int j = 0; j < 4; j++) {
            const int col = bn + g.wc + j * 8 + cq;
            const float b0 = bias[col], b1 = bias[col + 1];
            const int row0 = bm + g.wr + mt * 16 + rq;
            *(float2*)(C + (size_t)row0 * D_MODEL + col) =
                make_float2(g.acc[mt][j][0] + b0, g.acc[mt][j][1] + b1);
            *(float2*)(C + (size_t)(row0 + 8) * D_MODEL + col) =
                make_float2(g.acc[mt][j][2] + b0, g.acc[mt][j][3] + b1);
        }
    }
}

// ---------------------------------------------------------------------------
// Flash attention, single-fp16 mma.sync, causal. Paired Q tiles.
// S = Q K^T (1 term);  PV = P V (1 term). 3-stage KV ring, 2 CTAs/SM.
// ---------------------------------------------------------------------------
#define ALD 72
#define AQ_B  (128 * ALD * 2)          // 18432 B (single Q matrix)
#define AM_B  (64 * ALD * 2)           // 9216 B per K/V matrix
#define AST_B (2 * AM_B)               // stage: Kh,Vh = 18432 B
#define ATTN_SMEM (AQ_B + 3 * AST_B)   // 73728 B -> 2 CTAs/SM

#define SCL 0.18033688f                // 0.125 * log2(e)

__global__ __launch_bounds__(256, 2) void attn_mma(
    const __half* __restrict__ Qhp,
    const __half* __restrict__ Kh, const __half* __restrict__ Vh,
    __half* __restrict__ Oh)
{
    extern __shared__ __align__(128) char smc[];
    const uint32_t smb = smem_u32(smc);
    const int tid = threadIdx.x;
    const int wid = tid >> 5;
    const int lane = tid & 31;
    const int bx = blockIdx.x;
    const int h = blockIdx.y, b = blockIdx.z;
    const size_t rc0 = (size_t)b * SEQ * D_MODEL + h * HDIM;

    const int wr = wid * 16;
    const uint32_t lrow = lane & 15;
    const uint32_t lc16 = (lane >> 4) * 16;

    auto load_q = [&](int q0) {
#pragma unroll
        for (int it = 0; it < 4; it++) {
            int idx = tid + it * 256;           // 0..1023
            int r = idx >> 3, u = idx & 7;
            CP16(smb + (uint32_t)(r * ALD + u * 8) * 2,
                 Qhp + rc0 + (size_t)(q0 + r) * D_MODEL + u * 8);
        }
    };
    auto load_kv = [&](int kt, int stg) {
        const uint32_t sb = smb + AQ_B + stg * AST_B;
#pragma unroll
        for (int it = 0; it < 4; it++) {
            int t = tid + it * 256;
            int mtx = t >> 9;                   // 0:Kh 1:Vh
            int idx = t & 511, r = idx >> 3, u = idx & 7;
            const __half* src = (mtx == 0) ? Kh : Vh;
            CP16(sb + mtx * AM_B + (uint32_t)(r * ALD + u * 8) * 2,
                 src + rc0 + (size_t)(kt * 64 + r) * D_MODEL + u * 8);
        }
    };

    for (int half = 0; half < 2; half++) {
        const int qt = half ? (7 - bx) : (8 + bx);
        const int q0 = qt * 128;
        const int ktEnd = 2 * qt + 2;

        float o[8][4];
#pragma unroll
        for (int nt = 0; nt < 8; nt++)
#pragma unroll
            for (int c = 0; c < 4; c++) o[nt][c] = 0.0f;
        float m0 = -1e30f, m1 = -1e30f, l0 = 0.0f, l1 = 0.0f;
        uint32_t qh[4][4];

        load_q(q0);
        load_kv(0, 0);
        CP_COMMIT();
        if (1 < ktEnd) load_kv(1, 1);
        CP_COMMIT();

        for (int kt = 0; kt < ktEnd; kt++) {
            CP_WAIT(1);
            __syncthreads();
            if (kt + 2 < ktEnd) load_kv(kt + 2, (kt + 2) % 3);
            CP_COMMIT();

            if (kt == 0) {
#pragma unroll
                for (int ks = 0; ks < 4; ks++) {
                    uint32_t a1 = smb + (uint32_t)((wr + lrow) * ALD) * 2 + ks * 32 + lc16;
                    LDSM4(qh[ks][0], qh[ks][1], qh[ks][2], qh[ks][3], a1);
                }
            }

            const uint32_t sb = smb + AQ_B + (kt % 3) * AST_B;

            // ---- S = Q K^T (single term) ----
            float s[8][4];
#pragma unroll
            for (int nt = 0; nt < 8; nt++)
#pragma unroll
                for (int c = 0; c < 4; c++) s[nt][c] = 0.0f;

#pragma unroll
            for (int ks = 0; ks < 4; ks++) {
                uint32_t kf[4][4];
#pragma unroll
                for (int ng = 0; ng < 4; ng++) {
                    uint32_t a1 = sb + (uint32_t)((ng * 16 + lrow) * ALD) * 2 + ks * 32 + lc16;
                    LDSM4(kf[ng][0], kf[ng][1], kf[ng][2], kf[ng][3], a1);
                }
#pragma unroll
                for (int nt = 0; nt < 8; nt++)
                    MMA_F16(s[nt], qh[ks], kf[nt >> 1][nt & 1], kf[nt >> 1][(nt & 1) + 2]);
            }

#pragma unroll
            for (int nt = 0; nt < 8; nt++)
#pragma unroll
                for (int c = 0; c < 4; c++) s[nt][c] *= SCL;   // log2-domain

            // ---- causal mask (diagonal tiles only) ----
            if (kt * 64 + 63 > q0 + wr) {
                const int r0 = q0 + wr + (lane >> 2);
#pragma unroll
                for (int nt = 0; nt < 8; nt++) {
                    const int c0 = kt * 64 + nt * 8 + 2 * (lane & 3);
                    if (c0 > r0)         s[nt][0] = -1e30f;
                    if (c0 + 1 > r0)     s[nt][1] = -1e30f;
                    if (c0 > r0 + 8)     s[nt][2] = -1e30f;
                    if (c0 + 1 > r0 + 8) s[nt][3] = -1e30f;
                }
            }

            // ---- online softmax (base-2, quad shuffles) ----
            float mx0 = -1e30f, mx1 = -1e30f;
#pragma unroll
            for (int nt = 0; nt < 8; nt++) {
                mx0 = fmaxf(mx0, fmaxf(s[nt][0], s[nt][1]));
                mx1 = fmaxf(mx1, fmaxf(s[nt][2], s[nt][3]));
            }
            mx0 = fmaxf(mx0, __shfl_xor_sync(0xffffffffu, mx0, 1));
            mx0 = fmaxf(mx0, __shfl_xor_sync(0xffffffffu, mx0, 2));
            mx1 = fmaxf(mx1, __shfl_xor_sync(0xffffffffu, mx1, 1));
            mx1 = fmaxf(mx1, __shfl_xor_sync(0xffffffffu, mx1, 2));
            const float n0 = fmaxf(m0, mx0), n1 = fmaxf(m1, mx1);
            const float cr0 = exp2f(m0 - n0), cr1 = exp2f(m1 - n1);
            m0 = n0; m1 = n1;
            float sum0 = 0.0f, sum1 = 0.0f;
#pragma unroll
            for (int nt = 0; nt < 8; nt++) {
                s[nt][0] = exp2f(s[nt][0] - n0); sum0 += s[nt][0];
                s[nt][1] = exp2f(s[nt][1] - n0); sum0 += s[nt][1];
                s[nt][2] = exp2f(s[nt][2] - n1); sum1 += s[nt][2];
                s[nt][3] = exp2f(s[nt][3] - n1); sum1 += s[nt][3];
            }
            sum0 += __shfl_xor_sync(0xffffffffu, sum0, 1);
            sum0 += __shfl_xor_sync(0xffffffffu, sum0, 2);
            sum1 += __shfl_xor_sync(0xffffffffu, sum1, 1);
            sum1 += __shfl_xor_sync(0xffffffffu, sum1, 2);
            l0 = l0 * cr0 + sum0;
            l1 = l1 * cr1 + sum1;
#pragma unroll
            for (int nt = 0; nt < 8; nt++) {
                o[nt][0] *= cr0; o[nt][1] *= cr0;
                o[nt][2] *= cr1; o[nt][3] *= cr1;
            }

            // ---- P fragments: single fp16 ----
            uint32_t ph[4][4];
#pragma unroll
            for (int ks = 0; ks < 4; ks++) {
                ph[ks][0] = pack2h(s[2 * ks][0], s[2 * ks][1]);
                ph[ks][1] = pack2h(s[2 * ks][2], s[2 * ks][3]);
                ph[ks][2] = pack2h(s[2 * ks + 1][0], s[2 * ks + 1][1]);
                ph[ks][3] = pack2h(s[2 * ks + 1][2], s[2 * ks + 1][3]);
            }

            // ---- O += P V (1 term) ----
#pragma unroll
            for (int ks = 0; ks < 4; ks++) {
                uint32_t vh[4][4];
#pragma unroll
                for (int ng = 0; ng < 4; ng++) {
                    uint32_t a1 = sb + AM_B + (uint32_t)((ks * 16 + lrow) * ALD) * 2 + ng * 32 + lc16;
                    LDSM4T(vh[ng][0], vh[ng][1], vh[ng][2], vh[ng][3], a1);
                }
#pragma unroll
                for (int nt = 0; nt < 8; nt++)
                    MMA_F16(o[nt], ph[ks], vh[nt >> 1][(nt & 1) * 2], vh[nt >> 1][(nt & 1) * 2 + 1]);
            }
        }

        // ---- epilogue: normalize, fp16 store ----
        const float i0 = 1.0f / l0, i1 = 1.0f / l1;
        const size_t r0 = (size_t)(b * SEQ + q0 + wr + (lane >> 2));
        const int colb = h * HDIM + 2 * (lane & 3);
#pragma unroll
        for (int nt = 0; nt < 8; nt++) {
            const int col = colb + nt * 8;
            *(uint32_t*)(Oh + r0 * D_MODEL + col) = pack2h(o[nt][0] * i0, o[nt][1] * i0);
            *(uint32_t*)(Oh + (r0 + 8) * D_MODEL + col) = pack2h(o[nt][2] * i1, o[nt][3] * i1);
        }

        // drain before next tile reuses Q/KV smem
        CP_WAIT(0);
        __syncthreads();
    }
}

// ---------------------------------------------------------------------------
// Launch
// ---------------------------------------------------------------------------
extern "C" void kernel_launch(void* const* d_in, const int* in_sizes, int n_in,
                              void* d_out, int out_size)
{
    (void)in_sizes; (void)n_in; (void)out_size;
    const float* x  = (const float*)d_in[0];
    const float* Wq = (const float*)d_in[1];
    const float* bq = (const float*)d_in[2];
    const float* Wk = (const float*)d_in[3];
    const float* bk = (const float*)d_in[4];
    const float* Wv = (const float*)d_in[5];
    const float* bv = (const float*)d_in[6];
    const float* Wo = (const float*)d_in[7];
    const float* bo = (const float*)d_in[8];
    float* out = (float*)d_out;

    __half *xh, *wh, *qh, *kh, *vh, *oh;
    cudaGetSymbolAddress((void**)&xh, g_xh);
    cudaGetSymbolAddress((void**)&wh, g_wh);
    cudaGetSymbolAddress((void**)&qh, g_qh);
    cudaGetSymbolAddress((void**)&kh, g_kh);
    cudaGetSymbolAddress((void**)&vh, g_vh);
    cudaGetSymbolAddress((void**)&oh, g_oh);

    cudaFuncSetAttribute(attn_mma,
                         cudaFuncAttributeMaxDynamicSharedMemorySize, ATTN_SMEM);
    cudaFuncSetAttribute(gemm_qkv,
                         cudaFuncAttributeMaxDynamicSharedMemorySize, GEMM_SMEM);
    cudaFuncSetAttribute(gemm_out,
                         cudaFuncAttributeMaxDynamicSharedMemorySize, GEMM_SMEM);

    prep_kernel<<<PREP_BLOCKS, 256>>>(x, Wq, Wk, Wv, Wo, xh, wh);

    dim3 gQKV(3 * D_MODEL / 128, MTOT / 128);   // (24, 32)
    gemm_qkv<<<gQKV, 256, GEMM_SMEM>>>(xh, wh, bq, bk, bv, qh, kh, vh);

    dim3 gAttn(SEQ / 256, NHEAD, BATCH);        // (8, 16, 2) - paired tiles
    attn_mma<<<gAttn, 256, ATTN_SMEM>>>(qh, kh, vh, oh);

    dim3 gOut(D_MODEL / 128, MTOT / 128);       // (8, 32)
    gemm_out<<<gOut, 256, GEMM_SMEM>>>(oh, wh + (size_t)3 * WN, bo, out);
}

// round 13
// speedup vs baseline: 1.7396x; 1.0450x over previous
#include <cuda_runtime.h>
#include <cuda_fp16.h>
#include <cstdint>
#include <cstddef>

#define D_MODEL 1024
#define SEQ     2048
#define BATCH   2
#define NHEAD   16
#define HDIM    64
#define MTOT    (BATCH * SEQ)          // 4096 rows

// ---------------------------------------------------------------------------
// Scratch (no cudaMalloc allowed) — all single fp16
// ---------------------------------------------------------------------------
__device__ __half g_xh[MTOT * D_MODEL];
__device__ __half g_wh[4 * D_MODEL * D_MODEL];   // Wq|Wk|Wv|Wo rows contiguous
__device__ __half g_qh[MTOT * D_MODEL];
__device__ __half g_kh[MTOT * D_MODEL];
__device__ __half g_vh[MTOT * D_MODEL];
__device__ __half g_oh[MTOT * D_MODEL];

// ---------------------------------------------------------------------------
// PTX helpers (sm_100-safe)
// ---------------------------------------------------------------------------
__device__ __forceinline__ uint32_t smem_u32(const void* p) {
    uint32_t a;
    asm("{ .reg .u64 t; cvta.to.shared.u64 t, %1; cvt.u32.u64 %0, t; }" : "=r"(a) : "l"(p));
    return a;
}
#define CP16(dst, src) \
    asm volatile("cp.async.cg.shared.global [%0], [%1], 16;" :: "r"(dst), "l"(src))
#define CP_COMMIT() asm volatile("cp.async.commit_group;" ::: "memory")
#define CP_WAIT(n)  asm volatile("cp.async.wait_group %0;" :: "n"(n) : "memory")

#define LDSM4(r0, r1, r2, r3, addr) \
    asm volatile("ldmatrix.sync.aligned.m8n8.x4.shared.b16 {%0,%1,%2,%3}, [%4];" \
                 : "=r"(r0), "=r"(r1), "=r"(r2), "=r"(r3) : "r"(addr))
#define LDSM4T(r0, r1, r2, r3, addr) \
    asm volatile("ldmatrix.sync.aligned.m8n8.x4.trans.shared.b16 {%0,%1,%2,%3}, [%4];" \
                 : "=r"(r0), "=r"(r1), "=r"(r2), "=r"(r3) : "r"(addr))

#define MMA_F16(d, a, b0, b1) \
    asm volatile("mma.sync.aligned.m16n8k16.row.col.f32.f16.f16.f32 " \
                 "{%0,%1,%2,%3}, {%4,%5,%6,%7}, {%8,%9}, {%0,%1,%2,%3};" \
                 : "+f"((d)[0]), "+f"((d)[1]), "+f"((d)[2]), "+f"((d)[3]) \
                 : "r"((a)[0]), "r"((a)[1]), "r"((a)[2]), "r"((a)[3]), \
                   "r"(b0), "r"(b1))

__device__ __forceinline__ uint32_t pack2h(float a, float b) {
    __half2 h = __floats2half2_rn(a, b);
    return *(uint32_t*)&h;
}

// ---------------------------------------------------------------------------
// Merged preprocessing: fp32 -> fp16 cvt of x and 4 weights. MLP=4.
// ---------------------------------------------------------------------------
#define N4X (MTOT * D_MODEL / 4)       // 1048576
#define N4W (D_MODEL * D_MODEL / 4)    // 262144 = 1<<18
#define WN  (D_MODEL * D_MODEL)
#define NPREP (N4X + 4 * N4W)          // 2097152
#define PREP_BLOCKS (NPREP / (256 * 4))  // 2048

__global__ __launch_bounds__(256) void prep_kernel(
    const float* __restrict__ x,
    const float* __restrict__ Wq, const float* __restrict__ Wk,
    const float* __restrict__ Wv, const float* __restrict__ Wo,
    __half* __restrict__ xh, __half* __restrict__ wh)
{
    const int stride = PREP_BLOCKS * 256;
#pragma unroll
    for (int rep = 0; rep < 4; rep++) {
        int i = blockIdx.x * 256 + threadIdx.x + rep * stride;
        const float* src;
        __half2* dst;
        int w;
        if (i < N4X) {
            src = x; dst = (__half2*)xh; w = i;
        } else {
            int t = i - N4X;
            int j = t >> 18;
            w = t & (N4W - 1);
            src = (j == 0) ? Wq : (j == 1) ? Wk : (j == 2) ? Wv : Wo;
            dst = (__half2*)(wh + (size_t)j * WN);
        }
        float4 v = ((const float4*)src)[w];
        dst[2 * w] = __floats2half2_rn(v.x, v.y);
        dst[2 * w + 1] = __floats2half2_rn(v.z, v.w);
    }
}

// ---------------------------------------------------------------------------
// GEMM core: 128x128 C tile, BK=64 chunks, K=1024 -> 16 chunks, single fp16 A.
// 3-stage cp.async ring, ONE __syncthreads per chunk. Hoisted addresses.
// ---------------------------------------------------------------------------
#define GK 1024
#define GLD 72                          // row stride in fp16 (144 B, conflict-free)
#define GTB  (128 * GLD * 2)            // 18432 B per matrix tile
#define GSTB (2 * GTB)                  // 36864 B per stage (A + B)
#define GEMM_SMEM (3 * GSTB)            // 110592 B -> 2 CTAs/SM
#define NCH 16

struct GemmCore {
    uint32_t smb;
    int lane, wr, wc;
    uint32_t dstA[4];                   // smem dst byte offsets (A; W = +GTB)
    uint32_t offA[4], offW[4];          // gmem element offsets (32-bit)
    uint32_t aRow[4], bRow[2];          // LDSM smem row byte offsets
    float acc[4][4][4];

    __device__ __forceinline__ void init(uint32_t smb_, int tid, int bm, int bn) {
        smb = smb_;
        const int wid = tid >> 5;
        lane = tid & 31;
        wr = (wid & 1) * 64; wc = (wid >> 1) * 32;
#pragma unroll
        for (int it = 0; it < 4; it++) {
            int idx = tid + it * 256;
            int r = idx >> 3, u = idx & 7;
            dstA[it] = (uint32_t)(r * GLD) * 2 + u * 16;
            offA[it] = (uint32_t)(bm + r) * GK + u * 8;
            offW[it] = (uint32_t)(bn + r) * GK + u * 8;
        }
#pragma unroll
        for (int mt = 0; mt < 4; mt++)
            aRow[mt] = (uint32_t)((wr + mt * 16 + (lane & 15)) * GLD) * 2 + (lane >> 4) * 16;
#pragma unroll
        for (int ng = 0; ng < 2; ng++)
            bRow[ng] = GTB + (uint32_t)((wc + ng * 16 + (lane & 15)) * GLD) * 2 + (lane >> 4) * 16;
#pragma unroll
        for (int mt = 0; mt < 4; mt++)
#pragma unroll
            for (int j = 0; j < 4; j++)
#pragma unroll
                for (int r = 0; r < 4; r++) acc[mt][j][r] = 0.0f;
    }
    __device__ __forceinline__ void load_chunk(
        const __half* __restrict__ A, const __half* __restrict__ W,
        int c, int stg) {
        const __half* Ap = A + c * 64;
        const __half* Wp = W + c * 64;
        const uint32_t sa = smb + stg * GSTB;
#pragma unroll
        for (int it = 0; it < 4; it++)
            CP16(sa + dstA[it], Ap + offA[it]);
#pragma unroll
        for (int it = 0; it < 4; it++)
            CP16(sa + GTB + dstA[it], Wp + offW[it]);
    }
    __device__ __forceinline__ void compute(int stg) {
        const uint32_t sa = smb + stg * GSTB;
#pragma unroll
        for (int ks = 0; ks < 4; ks++) {
            const uint32_t colb = ks * 32;
            uint32_t a[4][4], b[2][4];
#pragma unroll
            for (int mt = 0; mt < 4; mt++)
                LDSM4(a[mt][0], a[mt][1], a[mt][2], a[mt][3], sa + aRow[mt] + colb);
#pragma unroll
            for (int ng = 0; ng < 2; ng++)
                LDSM4(b[ng][0], b[ng][1], b[ng][2], b[ng][3], sa + bRow[ng] + colb);
#pragma unroll
            for (int mt = 0; mt < 4; mt++)
#pragma unroll
                for (int j = 0; j < 4; j++)
                    MMA_F16(acc[mt][j], a[mt], b[j >> 1][j & 1], b[j >> 1][(j & 1) + 2]);
        }
    }
    __device__ __forceinline__ void run(
        const __half* __restrict__ A, const __half* __restrict__ W) {
        load_chunk(A, W, 0, 0); CP_COMMIT();
        load_chunk(A, W, 1, 1); CP_COMMIT();
        for (int c = 0; c < NCH; c++) {
            CP_WAIT(1);
            __syncthreads();
            if (c + 2 < NCH) load_chunk(A, W, c + 2, (c + 2) % 3);
            CP_COMMIT();
            compute(c % 3);
        }
    }
};

// ---------------------------------------------------------------------------
// Fused QKV GEMM (per batch): N=3072 over contiguous Wq|Wk|Wv.
// bm0 = batch row offset. bn>>10 selects Q/K/V dst. Outputs single fp16.
// ---------------------------------------------------------------------------
__global__ __launch_bounds__(256, 2) void gemm_qkv(
    const __half* __restrict__ A, const __half* __restrict__ W,
    const float* __restrict__ bq, const float* __restrict__ bk,
    const float* __restrict__ bv,
    __half* __restrict__ Qh, __half* __restrict__ Kh, __half* __restrict__ Vh,
    int bm0)
{
    extern __shared__ __align__(128) char smg[];
    const int bn = blockIdx.x * 128;            // 0..2944
    const int bm = bm0 + blockIdx.y * 128;
    GemmCore g;
    g.init(smem_u32(smg), threadIdx.x, bm, bn);
    g.run(A, W);

    const int bh = bn >> 10;                    // 0:Q 1:K 2:V
    const int cb = bn & 1023;
    const float* bias = (bh == 0) ? bq : (bh == 1) ? bk : bv;
    __half* dst = (bh == 0) ? Qh : (bh == 1) ? Kh : Vh;
    const int rq = g.lane >> 2;
    const int cq = (g.lane & 3) * 2;
#pragma unroll
    for (int mt = 0; mt < 4; mt++) {
#pragma unroll
        for (int j = 0; j < 4; j++) {
            const int col = cb + g.wc + j * 8 + cq;
            const float b0 = bias[col], b1 = bias[col + 1];
            const int row0 = bm + g.wr + mt * 16 + rq;
            *(__half2*)(dst + (size_t)row0 * D_MODEL + col) =
                __floats2half2_rn(g.acc[mt][j][0] + b0, g.acc[mt][j][1] + b1);
            *(__half2*)(dst + (size_t)(row0 + 8) * D_MODEL + col) =
                __floats2half2_rn(g.acc[mt][j][2] + b0, g.acc[mt][j][3] + b1);
        }
    }
}

// ---------------------------------------------------------------------------
// Output projection GEMM (per batch): fp32 out + bias, N=1024.
// ---------------------------------------------------------------------------
__global__ __launch_bounds__(256, 2) void gemm_out(
    const __half* __restrict__ A, const __half* __restrict__ W,
    const float* __restrict__ bias, float* __restrict__ C, int bm0)
{
    extern __shared__ __align__(128) char smg[];
    const int bn = blockIdx.x * 128;
    const int bm = bm0 + blockIdx.y * 128;
    GemmCore g;
    g.init(smem_u32(smg), threadIdx.x, bm, bn);
    g.run(A, W);

    const int rq = g.lane >> 2;
    const int cq = (g.lane & 3) * 2;
#pragma unroll
    for (int mt = 0; mt < 4; mt++) {
#pragma unroll
        for (int j = 0; j < 4; j++) {
            const int col = bn + g.wc + j * 8 + cq;
            const float b0 = bias[col], b1 = bias[col + 1];
            const int row0 = bm + g.wr + mt * 16 + rq;
            *(float2*)(C + (size_t)row0 * D_MODEL + col) =
                make_float2(g.acc[mt][j][0] + b0, g.acc[mt][j][1] + b1);
            *(float2*)(C + (size_t)(row0 + 8) * D_MODEL + col) =
                make_float2(g.acc[mt][j][2] + b0, g.acc[mt][j][3] + b1);
        }
    }
}

// ---------------------------------------------------------------------------
// Flash attention, single-fp16 mma.sync, causal (per batch). Paired Q tiles.
// S = Q K^T (1 term);  PV = P V (1 term). 3-stage KV ring, 2 CTAs/SM.
// ---------------------------------------------------------------------------
#define ALD 72
#define AQ_B  (128 * ALD * 2)          // 18432 B (single Q matrix)
#define AM_B  (64 * ALD * 2)           // 9216 B per K/V matrix
#define AST_B (2 * AM_B)               // stage: Kh,Vh = 18432 B
#define ATTN_SMEM (AQ_B + 3 * AST_B)   // 73728 B -> 2 CTAs/SM

#define SCL 0.18033688f                // 0.125 * log2(e)

__global__ __launch_bounds__(256, 2) void attn_mma(
    const __half* __restrict__ Qhp,
    const __half* __restrict__ Kh, const __half* __restrict__ Vh,
    __half* __restrict__ Oh, int b)
{
    extern __shared__ __align__(128) char smc[];
    const uint32_t smb = smem_u32(smc);
    const int tid = threadIdx.x;
    const int wid = tid >> 5;
    const int lane = tid & 31;
    const int bx = blockIdx.x;
    const int h = blockIdx.y;
    const size_t rc0 = (size_t)b * SEQ * D_MODEL + h * HDIM;

    const int wr = wid * 16;
    const uint32_t lrow = lane & 15;
    const uint32_t lc16 = (lane >> 4) * 16;

    auto load_q = [&](int q0) {
#pragma unroll
        for (int it = 0; it < 4; it++) {
            int idx = tid + it * 256;           // 0..1023
            int r = idx >> 3, u = idx & 7;
            CP16(smb + (uint32_t)(r * ALD + u * 8) * 2,
                 Qhp + rc0 + (size_t)(q0 + r) * D_MODEL + u * 8);
        }
    };
    auto load_kv = [&](int kt, int stg) {
        const uint32_t sb = smb + AQ_B + stg * AST_B;
#pragma unroll
        for (int it = 0; it < 4; it++) {
            int t = tid + it * 256;
            int mtx = t >> 9;                   // 0:Kh 1:Vh
            int idx = t & 511, r = idx >> 3, u = idx & 7;
            const __half* src = (mtx == 0) ? Kh : Vh;
            CP16(sb + mtx * AM_B + (uint32_t)(r * ALD + u * 8) * 2,
                 src + rc0 + (size_t)(kt * 64 + r) * D_MODEL + u * 8);
        }
    };

    for (int half = 0; half < 2; half++) {
        const int qt = half ? (7 - bx) : (8 + bx);
        const int q0 = qt * 128;
        const int ktEnd = 2 * qt + 2;

        float o[8][4];
#pragma unroll
        for (int nt = 0; nt < 8; nt++)
#pragma unroll
            for (int c = 0; c < 4; c++) o[nt][c] = 0.0f;
        float m0 = -1e30f, m1 = -1e30f, l0 = 0.0f, l1 = 0.0f;
        uint32_t qh[4][4];

        load_q(q0);
        load_kv(0, 0);
        CP_COMMIT();
        if (1 < ktEnd) load_kv(1, 1);
        CP_COMMIT();

        for (int kt = 0; kt < ktEnd; kt++) {
            CP_WAIT(1);
            __syncthreads();
            if (kt + 2 < ktEnd) load_kv(kt + 2, (kt + 2) % 3);
            CP_COMMIT();

            if (kt == 0) {
#pragma unroll
                for (int ks = 0; ks < 4; ks++) {
                    uint32_t a1 = smb + (uint32_t)((wr + lrow) * ALD) * 2 + ks * 32 + lc16;
                    LDSM4(qh[ks][0], qh[ks][1], qh[ks][2], qh[ks][3], a1);
                }
            }

            const uint32_t sb = smb + AQ_B + (kt % 3) * AST_B;

            // ---- S = Q K^T (single term) ----
            float s[8][4];
#pragma unroll
            for (int nt = 0; nt < 8; nt++)
#pragma unroll
                for (int c = 0; c < 4; c++) s[nt][c] = 0.0f;

#pragma unroll
            for (int ks = 0; ks < 4; ks++) {
                uint32_t kf[4][4];
#pragma unroll
                for (int ng = 0; ng < 4; ng++) {
                    uint32_t a1 = sb + (uint32_t)((ng * 16 + lrow) * ALD) * 2 + ks * 32 + lc16;
                    LDSM4(kf[ng][0], kf[ng][1], kf[ng][2], kf[ng][3], a1);
                }
#pragma unroll
                for (int nt = 0; nt < 8; nt++)
                    MMA_F16(s[nt], qh[ks], kf[nt >> 1][nt & 1], kf[nt >> 1][(nt & 1) + 2]);
            }

#pragma unroll
            for (int nt = 0; nt < 8; nt++)
#pragma unroll
                for (int c = 0; c < 4; c++) s[nt][c] *= SCL;   // log2-domain

            // ---- causal mask (diagonal tiles only) ----
            if (kt * 64 + 63 > q0 + wr) {
                const int r0 = q0 + wr + (lane >> 2);
#pragma unroll
                for (int nt = 0; nt < 8; nt++) {
                    const int c0 = kt * 64 + nt * 8 + 2 * (lane & 3);
                    if (c0 > r0)         s[nt][0] = -1e30f;
                    if (c0 + 1 > r0)     s[nt][1] = -1e30f;
                    if (c0 > r0 + 8)     s[nt][2] = -1e30f;
                    if (c0 + 1 > r0 + 8) s[nt][3] = -1e30f;
                }
            }

            // ---- online softmax (base-2, quad shuffles) ----
            float mx0 = -1e30f, mx1 = -1e30f;
#pragma unroll
            for (int nt = 0; nt < 8; nt++) {
                mx0 = fmaxf(mx0, fmaxf(s[nt][0], s[nt][1]));
                mx1 = fmaxf(mx1, fmaxf(s[nt][2], s[nt][3]));
            }
            mx0 = fmaxf(mx0, __shfl_xor_sync(0xffffffffu, mx0, 1));
            mx0 = fmaxf(mx0, __shfl_xor_sync(0xffffffffu, mx0, 2));
            mx1 = fmaxf(mx1, __shfl_xor_sync(0xffffffffu, mx1, 1));
            mx1 = fmaxf(mx1, __shfl_xor_sync(0xffffffffu, mx1, 2));
            const float n0 = fmaxf(m0, mx0), n1 = fmaxf(m1, mx1);
            const float cr0 = exp2f(m0 - n0), cr1 = exp2f(m1 - n1);
            m0 = n0; m1 = n1;
            float sum0 = 0.0f, sum1 = 0.0f;
#pragma unroll
            for (int nt = 0; nt < 8; nt++) {
                s[nt][0] = exp2f(s[nt][0] - n0); sum0 += s[nt][0];
                s[nt][1] = exp2f(s[nt][1] - n0); sum0 += s[nt][1];
                s[nt][2] = exp2f(s[nt][2] - n1); sum1 += s[nt][2];
                s[nt][3] = exp2f(s[nt][3] - n1); sum1 += s[nt][3];
            }
            sum0 += __shfl_xor_sync(0xffffffffu, sum0, 1);
            sum0 += __shfl_xor_sync(0xffffffffu, sum0, 2);
            sum1 += __shfl_xor_sync(0xffffffffu, sum1, 1);
            sum1 += __shfl_xor_sync(0xffffffffu, sum1, 2);
            l0 = l0 * cr0 + sum0;
            l1 = l1 * cr1 + sum1;
#pragma unroll
            for (int nt = 0; nt < 8; nt++) {
                o[nt][0] *= cr0; o[nt][1] *= cr0;
                o[nt][2] *= cr1; o[nt][3] *= cr1;
            }

            // ---- P fragments: single fp16 ----
            uint32_t ph[4][4];
#pragma unroll
            for (int ks = 0; ks < 4; ks++) {
                ph[ks][0] = pack2h(s[2 * ks][0], s[2 * ks][1]);
                ph[ks][1] = pack2h(s[2 * ks][2], s[2 * ks][3]);
                ph[ks][2] = pack2h(s[2 * ks + 1][0], s[2 * ks + 1][1]);
                ph[ks][3] = pack2h(s[2 * ks + 1][2], s[2 * ks + 1][3]);
            }

            // ---- O += P V (1 term) ----
#pragma unroll
            for (int ks = 0; ks < 4; ks++) {
                uint32_t vh[4][4];
#pragma unroll
                for (int ng = 0; ng < 4; ng++) {
                    uint32_t a1 = sb + AM_B + (uint32_t)((ks * 16 + lrow) * ALD) * 2 + ng * 32 + lc16;
                    LDSM4T(vh[ng][0], vh[ng][1], vh[ng][2], vh[ng][3], a1);
                }
#pragma unroll
                for (int nt = 0; nt < 8; nt++)
                    MMA_F16(o[nt], ph[ks], vh[nt >> 1][(nt & 1) * 2], vh[nt >> 1][(nt & 1) * 2 + 1]);
            }
        }

        // ---- epilogue: normalize, fp16 store ----
        const float i0 = 1.0f / l0, i1 = 1.0f / l1;
        const size_t r0 = (size_t)(b * SEQ + q0 + wr + (lane >> 2));
        const int colb = h * HDIM + 2 * (lane & 3);
#pragma unroll
        for (int nt = 0; nt < 8; nt++) {
            const int col = colb + nt * 8;
            *(uint32_t*)(Oh + r0 * D_MODEL + col) = pack2h(o[nt][0] * i0, o[nt][1] * i0);
            *(uint32_t*)(Oh + (r0 + 8) * D_MODEL + col) = pack2h(o[nt][2] * i1, o[nt][3] * i1);
        }

        // drain before next tile reuses Q/KV smem
        CP_WAIT(0);
        __syncthreads();
    }
}

// ---------------------------------------------------------------------------
// Launch: two streams, one per batch, forked/joined via events so the
// captured graph branches. Batch pipelines overlap each other's tails.
// ---------------------------------------------------------------------------
extern "C" void kernel_launch(void* const* d_in, const int* in_sizes, int n_in,
                              void* d_out, int out_size)
{
    (void)in_sizes; (void)n_in; (void)out_size;
    const float* x  = (const float*)d_in[0];
    const float* Wq = (const float*)d_in[1];
    const float* bq = (const float*)d_in[2];
    const float* Wk = (const float*)d_in[3];
    const float* bk = (const float*)d_in[4];
    const float* Wv = (const float*)d_in[5];
    const float* bv = (const float*)d_in[6];
    const float* Wo = (const float*)d_in[7];
    const float* bo = (const float*)d_in[8];
    float* out = (float*)d_out;

    __half *xh, *wh, *qh, *kh, *vh, *oh;
    cudaGetSymbolAddress((void**)&xh, g_xh);
    cudaGetSymbolAddress((void**)&wh, g_wh);
    cudaGetSymbolAddress((void**)&qh, g_qh);
    cudaGetSymbolAddress((void**)&kh, g_kh);
    cudaGetSymbolAddress((void**)&vh, g_vh);
    cudaGetSymbolAddress((void**)&oh, g_oh);

    cudaFuncSetAttribute(attn_mma,
                         cudaFuncAttributeMaxDynamicSharedMemorySize, ATTN_SMEM);
    cudaFuncSetAttribute(gemm_qkv,
                         cudaFuncAttributeMaxDynamicSharedMemorySize, GEMM_SMEM);
    cudaFuncSetAttribute(gemm_out,
                         cudaFuncAttributeMaxDynamicSharedMemorySize, GEMM_SMEM);

    // One-time stream/event creation (first call = correctness run, not
    // under capture; later captures reuse them via fork/join events).
    static cudaStream_t s1 = nullptr;
    static cudaEvent_t eFork = nullptr, eJoin = nullptr;
    static bool init_ok = false;
    if (!init_ok) {
        bool ok = (cudaStreamCreateWithFlags(&s1, cudaStreamNonBlocking) == cudaSuccess);
        ok = ok && (cudaEventCreateWithFlags(&eFork, cudaEventDisableTiming) == cudaSuccess);
        ok = ok && (cudaEventCreateWithFlags(&eJoin, cudaEventDisableTiming) == cudaSuccess);
        init_ok = ok;
        if (!ok) s1 = nullptr;
    }

    prep_kernel<<<PREP_BLOCKS, 256>>>(x, Wq, Wk, Wv, Wo, xh, wh);

    const dim3 gQKV(3 * D_MODEL / 128, SEQ / 128);   // (24, 16) per batch
    const dim3 gAttn(SEQ / 256, NHEAD);              // (8, 16) per batch
    const dim3 gOut(D_MODEL / 128, SEQ / 128);       // (8, 16) per batch

    if (s1) {
        // fork: batch 1 stream waits on prep
        cudaEventRecord(eFork, 0);
        cudaStreamWaitEvent(s1, eFork, 0);

        // batch 0 on capture (default) stream
        gemm_qkv<<<gQKV, 256, GEMM_SMEM>>>(xh, wh, bq, bk, bv, qh, kh, vh, 0);
        attn_mma<<<gAttn, 256, ATTN_SMEM>>>(qh, kh, vh, oh, 0);
        gemm_out<<<gOut, 256, GEMM_SMEM>>>(oh, wh + (size_t)3 * WN, bo, out, 0);

        // batch 1 on side stream
        gemm_qkv<<<gQKV, 256, GEMM_SMEM, s1>>>(xh, wh, bq, bk, bv, qh, kh, vh, SEQ);
        attn_mma<<<gAttn, 256, ATTN_SMEM, s1>>>(qh, kh, vh, oh, 1);
        gemm_out<<<gOut, 256, GEMM_SMEM, s1>>>(oh, wh + (size_t)3 * WN, bo, out, SEQ);

        // join
        cudaEventRecord(eJoin, s1);
        cudaStreamWaitEvent(0, eJoin, 0);
    } else {
        // fallback: serial on default stream
        gemm_qkv<<<gQKV, 256, GEMM_SMEM>>>(xh, wh, bq, bk, bv, qh, kh, vh, 0);
        gemm_qkv<<<gQKV, 256, GEMM_SMEM>>>(xh, wh, bq, bk, bv, qh, kh, vh, SEQ);
        attn_mma<<<gAttn, 256, ATTN_SMEM>>>(qh, kh, vh, oh, 0);
        attn_mma<<<gAttn, 256, ATTN_SMEM>>>(qh, kh, vh, oh, 1);
        gemm_out<<<gOut, 256, GEMM_SMEM>>>(oh, wh + (size_t)3 * WN, bo, out, 0);
        gemm_out<<<gOut, 256, GEMM_SMEM>>>(oh, wh + (size_t)3 * WN, bo, out, SEQ);
    }
}

// round 14
// speedup vs baseline: 1.7398x; 1.0001x over previous
#include <cuda_runtime.h>
#include <cuda_fp16.h>
#include <cstdint>
#include <cstddef>

#define D_MODEL 1024
#define SEQ     2048
#define BATCH   2
#define NHEAD   16
#define HDIM    64
#define MTOT    (BATCH * SEQ)          // 4096 rows

// ---------------------------------------------------------------------------
// Scratch (no cudaMalloc allowed) — all single fp16
// ---------------------------------------------------------------------------
__device__ __half g_xh[MTOT * D_MODEL];
__device__ __half g_wh[4 * D_MODEL * D_MODEL];   // Wq|Wk|Wv|Wo rows contiguous
__device__ __half g_qh[MTOT * D_MODEL];
__device__ __half g_kh[MTOT * D_MODEL];
__device__ __half g_vh[MTOT * D_MODEL];
__device__ __half g_oh[MTOT * D_MODEL];

// ---------------------------------------------------------------------------
// PTX helpers (sm_100-safe)
// ---------------------------------------------------------------------------
__device__ __forceinline__ uint32_t smem_u32(const void* p) {
    uint32_t a;
    asm("{ .reg .u64 t; cvta.to.shared.u64 t, %1; cvt.u32.u64 %0, t; }" : "=r"(a) : "l"(p));
    return a;
}
#define CP16(dst, src) \
    asm volatile("cp.async.cg.shared.global [%0], [%1], 16;" :: "r"(dst), "l"(src))
#define CP_COMMIT() asm volatile("cp.async.commit_group;" ::: "memory")
#define CP_WAIT(n)  asm volatile("cp.async.wait_group %0;" :: "n"(n) : "memory")

#define LDSM4(r0, r1, r2, r3, addr) \
    asm volatile("ldmatrix.sync.aligned.m8n8.x4.shared.b16 {%0,%1,%2,%3}, [%4];" \
                 : "=r"(r0), "=r"(r1), "=r"(r2), "=r"(r3) : "r"(addr))
#define LDSM4T(r0, r1, r2, r3, addr) \
    asm volatile("ldmatrix.sync.aligned.m8n8.x4.trans.shared.b16 {%0,%1,%2,%3}, [%4];" \
                 : "=r"(r0), "=r"(r1), "=r"(r2), "=r"(r3) : "r"(addr))

#define MMA_F16(d, a, b0, b1) \
    asm volatile("mma.sync.aligned.m16n8k16.row.col.f32.f16.f16.f32 " \
                 "{%0,%1,%2,%3}, {%4,%5,%6,%7}, {%8,%9}, {%0,%1,%2,%3};" \
                 : "+f"((d)[0]), "+f"((d)[1]), "+f"((d)[2]), "+f"((d)[3]) \
                 : "r"((a)[0]), "r"((a)[1]), "r"((a)[2]), "r"((a)[3]), \
                   "r"(b0), "r"(b1))

__device__ __forceinline__ uint32_t pack2h(float a, float b) {
    __half2 h = __floats2half2_rn(a, b);
    return *(uint32_t*)&h;
}

// ---------------------------------------------------------------------------
// Merged preprocessing: fp32 -> fp16 cvt of x and 4 weights. MLP=4.
// ---------------------------------------------------------------------------
#define N4X (MTOT * D_MODEL / 4)       // 1048576
#define N4W (D_MODEL * D_MODEL / 4)    // 262144 = 1<<18
#define WN  (D_MODEL * D_MODEL)
#define NPREP (N4X + 4 * N4W)          // 2097152
#define PREP_BLOCKS (NPREP / (256 * 4))  // 2048

__global__ __launch_bounds__(256) void prep_kernel(
    const float* __restrict__ x,
    const float* __restrict__ Wq, const float* __restrict__ Wk,
    const float* __restrict__ Wv, const float* __restrict__ Wo,
    __half* __restrict__ xh, __half* __restrict__ wh)
{
    const int stride = PREP_BLOCKS * 256;
#pragma unroll
    for (int rep = 0; rep < 4; rep++) {
        int i = blockIdx.x * 256 + threadIdx.x + rep * stride;
        const float* src;
        __half2* dst;
        int w;
        if (i < N4X) {
            src = x; dst = (__half2*)xh; w = i;
        } else {
            int t = i - N4X;
            int j = t >> 18;
            w = t & (N4W - 1);
            src = (j == 0) ? Wq : (j == 1) ? Wk : (j == 2) ? Wv : Wo;
            dst = (__half2*)(wh + (size_t)j * WN);
        }
        float4 v = ((const float4*)src)[w];
        dst[2 * w] = __floats2half2_rn(v.x, v.y);
        dst[2 * w + 1] = __floats2half2_rn(v.z, v.w);
    }
}

// ---------------------------------------------------------------------------
// GEMM core: 128x128 C tile, BK=64 chunks, K=1024 -> 16 chunks, single fp16 A.
// 3-stage cp.async ring, ONE __syncthreads per chunk. Hoisted addresses.
// ---------------------------------------------------------------------------
#define GK 1024
#define GLD 72                          // row stride in fp16 (144 B, conflict-free)
#define GTB  (128 * GLD * 2)            // 18432 B per matrix tile
#define GSTB (2 * GTB)                  // 36864 B per stage (A + B)
#define GEMM_SMEM (3 * GSTB)            // 110592 B -> 2 CTAs/SM
#define NCH 16

struct GemmCore {
    uint32_t smb;
    int lane, wr, wc;
    uint32_t dstA[4];                   // smem dst byte offsets (A; W = +GTB)
    uint32_t offA[4], offW[4];          // gmem element offsets (32-bit)
    uint32_t aRow[4], bRow[2];          // LDSM smem row byte offsets
    float acc[4][4][4];

    __device__ __forceinline__ void init(uint32_t smb_, int tid, int bm, int bn) {
        smb = smb_;
        const int wid = tid >> 5;
        lane = tid & 31;
        wr = (wid & 1) * 64; wc = (wid >> 1) * 32;
#pragma unroll
        for (int it = 0; it < 4; it++) {
            int idx = tid + it * 256;
            int r = idx >> 3, u = idx & 7;
            dstA[it] = (uint32_t)(r * GLD) * 2 + u * 16;
            offA[it] = (uint32_t)(bm + r) * GK + u * 8;
            offW[it] = (uint32_t)(bn + r) * GK + u * 8;
        }
#pragma unroll
        for (int mt = 0; mt < 4; mt++)
            aRow[mt] = (uint32_t)((wr + mt * 16 + (lane & 15)) * GLD) * 2 + (lane >> 4) * 16;
#pragma unroll
        for (int ng = 0; ng < 2; ng++)
            bRow[ng] = GTB + (uint32_t)((wc + ng * 16 + (lane & 15)) * GLD) * 2 + (lane >> 4) * 16;
#pragma unroll
        for (int mt = 0; mt < 4; mt++)
#pragma unroll
            for (int j = 0; j < 4; j++)
#pragma unroll
                for (int r = 0; r < 4; r++) acc[mt][j][r] = 0.0f;
    }
    __device__ __forceinline__ void load_chunk(
        const __half* __restrict__ A, const __half* __restrict__ W,
        int c, int stg) {
        const __half* Ap = A + c * 64;
        const __half* Wp = W + c * 64;
        const uint32_t sa = smb + stg * GSTB;
#pragma unroll
        for (int it = 0; it < 4; it++)
            CP16(sa + dstA[it], Ap + offA[it]);
#pragma unroll
        for (int it = 0; it < 4; it++)
            CP16(sa + GTB + dstA[it], Wp + offW[it]);
    }
    __device__ __forceinline__ void compute(int stg) {
        const uint32_t sa = smb + stg * GSTB;
#pragma unroll
        for (int ks = 0; ks < 4; ks++) {
            const uint32_t colb = ks * 32;
            uint32_t a[4][4], b[2][4];
#pragma unroll
            for (int mt = 0; mt < 4; mt++)
                LDSM4(a[mt][0], a[mt][1], a[mt][2], a[mt][3], sa + aRow[mt] + colb);
#pragma unroll
            for (int ng = 0; ng < 2; ng++)
                LDSM4(b[ng][0], b[ng][1], b[ng][2], b[ng][3], sa + bRow[ng] + colb);
#pragma unroll
            for (int mt = 0; mt < 4; mt++)
#pragma unroll
                for (int j = 0; j < 4; j++)
                    MMA_F16(acc[mt][j], a[mt], b[j >> 1][j & 1], b[j >> 1][(j & 1) + 2]);
        }
    }
    __device__ __forceinline__ void run(
        const __half* __restrict__ A, const __half* __restrict__ W) {
        load_chunk(A, W, 0, 0); CP_COMMIT();
        load_chunk(A, W, 1, 1); CP_COMMIT();
        for (int c = 0; c < NCH; c++) {
            CP_WAIT(1);
            __syncthreads();
            if (c + 2 < NCH) load_chunk(A, W, c + 2, (c + 2) % 3);
            CP_COMMIT();
            compute(c % 3);
        }
    }
};

// ---------------------------------------------------------------------------
// Fused QKV GEMM (per batch): N=3072 over contiguous Wq|Wk|Wv.
// bm0 = batch row offset. bn>>10 selects Q/K/V dst. Outputs single fp16.
// ---------------------------------------------------------------------------
__global__ __launch_bounds__(256, 2) void gemm_qkv(
    const __half* __restrict__ A, const __half* __restrict__ W,
    const float* __restrict__ bq, const float* __restrict__ bk,
    const float* __restrict__ bv,
    __half* __restrict__ Qh, __half* __restrict__ Kh, __half* __restrict__ Vh,
    int bm0)
{
    extern __shared__ __align__(128) char smg[];
    const int bn = blockIdx.x * 128;            // 0..2944
    const int bm = bm0 + blockIdx.y * 128;
    GemmCore g;
    g.init(smem_u32(smg), threadIdx.x, bm, bn);
    g.run(A, W);

    const int bh = bn >> 10;                    // 0:Q 1:K 2:V
    const int cb = bn & 1023;
    const float* bias = (bh == 0) ? bq : (bh == 1) ? bk : bv;
    __half* dst = (bh == 0) ? Qh : (bh == 1) ? Kh : Vh;
    const int rq = g.lane >> 2;
    const int cq = (g.lane & 3) * 2;
#pragma unroll
    for (int mt = 0; mt < 4; mt++) {
#pragma unroll
        for (int j = 0; j < 4; j++) {
            const int col = cb + g.wc + j * 8 + cq;
            const float b0 = bias[col], b1 = bias[col + 1];
            const int row0 = bm + g.wr + mt * 16 + rq;
            *(__half2*)(dst + (size_t)row0 * D_MODEL + col) =
                __floats2half2_rn(g.acc[mt][j][0] + b0, g.acc[mt][j][1] + b1);
            *(__half2*)(dst + (size_t)(row0 + 8) * D_MODEL + col) =
                __floats2half2_rn(g.acc[mt][j][2] + b0, g.acc[mt][j][3] + b1);
        }
    }
}

// ---------------------------------------------------------------------------
// Output projection GEMM (per batch): fp32 out + bias, N=1024.
// ---------------------------------------------------------------------------
__global__ __launch_bounds__(256, 2) void gemm_out(
    const __half* __restrict__ A, const __half* __restrict__ W,
    const float* __restrict__ bias, float* __restrict__ C, int bm0)
{
    extern __shared__ __align__(128) char smg[];
    const int bn = blockIdx.x * 128;
    const int bm = bm0 + blockIdx.y * 128;
    GemmCore g;
    g.init(smem_u32(smg), threadIdx.x, bm, bn);
    g.run(A, W);

    const int rq = g.lane >> 2;
    const int cq = (g.lane & 3) * 2;
#pragma unroll
    for (int mt = 0; mt < 4; mt++) {
#pragma unroll
        for (int j = 0; j < 4; j++) {
            const int col = bn + g.wc + j * 8 + cq;
            const float b0 = bias[col], b1 = bias[col + 1];
            const int row0 = bm + g.wr + mt * 16 + rq;
            *(float2*)(C + (size_t)row0 * D_MODEL + col) =
                make_float2(g.acc[mt][j][0] + b0, g.acc[mt][j][1] + b1);
            *(float2*)(C + (size_t)(row0 + 8) * D_MODEL + col) =
                make_float2(g.acc[mt][j][2] + b0, g.acc[mt][j][3] + b1);
        }
    }
}

// ---------------------------------------------------------------------------
// Flash attention, single-fp16 mma.sync, causal (per batch). Paired Q tiles.
// S = Q K^T (1 term);  PV = P V (1 term). 3-stage KV ring, 2 CTAs/SM.
// ---------------------------------------------------------------------------
#define ALD 72
#define AQ_B  (128 * ALD * 2)          // 18432 B (single Q matrix)
#define AM_B  (64 * ALD * 2)           // 9216 B per K/V matrix
#define AST_B (2 * AM_B)               // stage: Kh,Vh = 18432 B
#define ATTN_SMEM (AQ_B + 3 * AST_B)   // 73728 B -> 2 CTAs/SM

#define SCL 0.18033688f                // 0.125 * log2(e)

__global__ __launch_bounds__(256, 2) void attn_mma(
    const __half* __restrict__ Qhp,
    const __half* __restrict__ Kh, const __half* __restrict__ Vh,
    __half* __restrict__ Oh, int b)
{
    extern __shared__ __align__(128) char smc[];
    const uint32_t smb = smem_u32(smc);
    const int tid = threadIdx.x;
    const int wid = tid >> 5;
    const int lane = tid & 31;
    const int bx = blockIdx.x;
    const int h = blockIdx.y;
    const size_t rc0 = (size_t)b * SEQ * D_MODEL + h * HDIM;

    const int wr = wid * 16;
    const uint32_t lrow = lane & 15;
    const uint32_t lc16 = (lane >> 4) * 16;

    auto load_q = [&](int q0) {
#pragma unroll
        for (int it = 0; it < 4; it++) {
            int idx = tid + it * 256;           // 0..1023
            int r = idx >> 3, u = idx & 7;
            CP16(smb + (uint32_t)(r * ALD + u * 8) * 2,
                 Qhp + rc0 + (size_t)(q0 + r) * D_MODEL + u * 8);
        }
    };
    auto load_kv = [&](int kt, int stg) {
        const uint32_t sb = smb + AQ_B + stg * AST_B;
#pragma unroll
        for (int it = 0; it < 4; it++) {
            int t = tid + it * 256;
            int mtx = t >> 9;                   // 0:Kh 1:Vh
            int idx = t & 511, r = idx >> 3, u = idx & 7;
            const __half* src = (mtx == 0) ? Kh : Vh;
            CP16(sb + mtx * AM_B + (uint32_t)(r * ALD + u * 8) * 2,
                 src + rc0 + (size_t)(kt * 64 + r) * D_MODEL + u * 8);
        }
    };

    for (int half = 0; half < 2; half++) {
        const int qt = half ? (7 - bx) : (8 + bx);
        const int q0 = qt * 128;
        const int ktEnd = 2 * qt + 2;

        float o[8][4];
#pragma unroll
        for (int nt = 0; nt < 8; nt++)
#pragma unroll
            for (int c = 0; c < 4; c++) o[nt][c] = 0.0f;
        float m0 = -1e30f, m1 = -1e30f, l0 = 0.0f, l1 = 0.0f;
        uint32_t qh[4][4];

        load_q(q0);
        load_kv(0, 0);
        CP_COMMIT();
        if (1 < ktEnd) load_kv(1, 1);
        CP_COMMIT();

        for (int kt = 0; kt < ktEnd; kt++) {
            CP_WAIT(1);
            __syncthreads();
            if (kt + 2 < ktEnd) load_kv(kt + 2, (kt + 2) % 3);
            CP_COMMIT();

            if (kt == 0) {
#pragma unroll
                for (int ks = 0; ks < 4; ks++) {
                    uint32_t a1 = smb + (uint32_t)((wr + lrow) * ALD) * 2 + ks * 32 + lc16;
                    LDSM4(qh[ks][0], qh[ks][1], qh[ks][2], qh[ks][3], a1);
                }
            }

            const uint32_t sb = smb + AQ_B + (kt % 3) * AST_B;

            // ---- S = Q K^T (single term) ----
            float s[8][4];
#pragma unroll
            for (int nt = 0; nt < 8; nt++)
#pragma unroll
                for (int c = 0; c < 4; c++) s[nt][c] = 0.0f;

#pragma unroll
            for (int ks = 0; ks < 4; ks++) {
                uint32_t kf[4][4];
#pragma unroll
                for (int ng = 0; ng < 4; ng++) {
                    uint32_t a1 = sb + (uint32_t)((ng * 16 + lrow) * ALD) * 2 + ks * 32 + lc16;
                    LDSM4(kf[ng][0], kf[ng][1], kf[ng][2], kf[ng][3], a1);
                }
#pragma unroll
                for (int nt = 0; nt < 8; nt++)
                    MMA_F16(s[nt], qh[ks], kf[nt >> 1][nt & 1], kf[nt >> 1][(nt & 1) + 2]);
            }

#pragma unroll
            for (int nt = 0; nt < 8; nt++)
#pragma unroll
                for (int c = 0; c < 4; c++) s[nt][c] *= SCL;   // log2-domain

            // ---- causal mask (diagonal tiles only) ----
            if (kt * 64 + 63 > q0 + wr) {
                const int r0 = q0 + wr + (lane >> 2);
#pragma unroll
                for (int nt = 0; nt < 8; nt++) {
                    const int c0 = kt * 64 + nt * 8 + 2 * (lane & 3);
                    if (c0 > r0)         s[nt][0] = -1e30f;
                    if (c0 + 1 > r0)     s[nt][1] = -1e30f;
                    if (c0 > r0 + 8)     s[nt][2] = -1e30f;
                    if (c0 + 1 > r0 + 8) s[nt][3] = -1e30f;
                }
            }

            // ---- online softmax (base-2, quad shuffles) ----
            float mx0 = -1e30f, mx1 = -1e30f;
#pragma unroll
            for (int nt = 0; nt < 8; nt++) {
                mx0 = fmaxf(mx0, fmaxf(s[nt][0], s[nt][1]));
                mx1 = fmaxf(mx1, fmaxf(s[nt][2], s[nt][3]));
            }
            mx0 = fmaxf(mx0, __shfl_xor_sync(0xffffffffu, mx0, 1));
            mx0 = fmaxf(mx0, __shfl_xor_sync(0xffffffffu, mx0, 2));
            mx1 = fmaxf(mx1, __shfl_xor_sync(0xffffffffu, mx1, 1));
            mx1 = fmaxf(mx1, __shfl_xor_sync(0xffffffffu, mx1, 2));
            const float n0 = fmaxf(m0, mx0), n1 = fmaxf(m1, mx1);
            const float cr0 = exp2f(m0 - n0), cr1 = exp2f(m1 - n1);
            m0 = n0; m1 = n1;
            float sum0 = 0.0f, sum1 = 0.0f;
#pragma unroll
            for (int nt = 0; nt < 8; nt++) {
                s[nt][0] = exp2f(s[nt][0] - n0); sum0 += s[nt][0];
                s[nt][1] = exp2f(s[nt][1] - n0); sum0 += s[nt][1];
                s[nt][2] = exp2f(s[nt][2] - n1); sum1 += s[nt][2];
                s[nt][3] = exp2f(s[nt][3] - n1); sum1 += s[nt][3];
            }
            sum0 += __shfl_xor_sync(0xffffffffu, sum0, 1);
            sum0 += __shfl_xor_sync(0xffffffffu, sum0, 2);
            sum1 += __shfl_xor_sync(0xffffffffu, sum1, 1);
            sum1 += __shfl_xor_sync(0xffffffffu, sum1, 2);
            l0 = l0 * cr0 + sum0;
            l1 = l1 * cr1 + sum1;
#pragma unroll
            for (int nt = 0; nt < 8; nt++) {
                o[nt][0] *= cr0; o[nt][1] *= cr0;
                o[nt][2] *= cr1; o[nt][3] *= cr1;
            }

            // ---- P fragments: single fp16 ----
            uint32_t ph[4][4];
#pragma unroll
            for (int ks = 0; ks < 4; ks++) {
                ph[ks][0] = pack2h(s[2 * ks][0], s[2 * ks][1]);
                ph[ks][1] = pack2h(s[2 * ks][2], s[2 * ks][3]);
                ph[ks][2] = pack2h(s[2 * ks + 1][0], s[2 * ks + 1][1]);
                ph[ks][3] = pack2h(s[2 * ks + 1][2], s[2 * ks + 1][3]);
            }

            // ---- O += P V (1 term) ----
#pragma unroll
            for (int ks = 0; ks < 4; ks++) {
                uint32_t vh[4][4];
#pragma unroll
                for (int ng = 0; ng < 4; ng++) {
                    uint32_t a1 = sb + AM_B + (uint32_t)((ks * 16 + lrow) * ALD) * 2 + ng * 32 + lc16;
                    LDSM4T(vh[ng][0], vh[ng][1], vh[ng][2], vh[ng][3], a1);
                }
#pragma unroll
                for (int nt = 0; nt < 8; nt++)
                    MMA_F16(o[nt], ph[ks], vh[nt >> 1][(nt & 1) * 2], vh[nt >> 1][(nt & 1) * 2 + 1]);
            }
        }

        // ---- epilogue: normalize, fp16 store ----
        const float i0 = 1.0f / l0, i1 = 1.0f / l1;
        const size_t r0 = (size_t)(b * SEQ + q0 + wr + (lane >> 2));
        const int colb = h * HDIM + 2 * (lane & 3);
#pragma unroll
        for (int nt = 0; nt < 8; nt++) {
            const int col = colb + nt * 8;
            *(uint32_t*)(Oh + r0 * D_MODEL + col) = pack2h(o[nt][0] * i0, o[nt][1] * i0);
            *(uint32_t*)(Oh + (r0 + 8) * D_MODEL + col) = pack2h(o[nt][2] * i1, o[nt][3] * i1);
        }

        // drain before next tile reuses Q/KV smem
        CP_WAIT(0);
        __syncthreads();
    }
}

// ---------------------------------------------------------------------------
// Launch: two streams, one per batch, forked/joined via events so the
// captured graph branches. Batch pipelines overlap each other's tails.
// ---------------------------------------------------------------------------
extern "C" void kernel_launch(void* const* d_in, const int* in_sizes, int n_in,
                              void* d_out, int out_size)
{
    (void)in_sizes; (void)n_in; (void)out_size;
    const float* x  = (const float*)d_in[0];
    const float* Wq = (const float*)d_in[1];
    const float* bq = (const float*)d_in[2];
    const float* Wk = (const float*)d_in[3];
    const float* bk = (const float*)d_in[4];
    const float* Wv = (const float*)d_in[5];
    const float* bv = (const float*)d_in[6];
    const float* Wo = (const float*)d_in[7];
    const float* bo = (const float*)d_in[8];
    float* out = (float*)d_out;

    __half *xh, *wh, *qh, *kh, *vh, *oh;
    cudaGetSymbolAddress((void**)&xh, g_xh);
    cudaGetSymbolAddress((void**)&wh, g_wh);
    cudaGetSymbolAddress((void**)&qh, g_qh);
    cudaGetSymbolAddress((void**)&kh, g_kh);
    cudaGetSymbolAddress((void**)&vh, g_vh);
    cudaGetSymbolAddress((void**)&oh, g_oh);

    cudaFuncSetAttribute(attn_mma,
                         cudaFuncAttributeMaxDynamicSharedMemorySize, ATTN_SMEM);
    cudaFuncSetAttribute(gemm_qkv,
                         cudaFuncAttributeMaxDynamicSharedMemorySize, GEMM_SMEM);
    cudaFuncSetAttribute(gemm_out,
                         cudaFuncAttributeMaxDynamicSharedMemorySize, GEMM_SMEM);

    // One-time stream/event creation (first call = correctness run, not
    // under capture; later captures reuse them via fork/join events).
    static cudaStream_t s1 = nullptr;
    static cudaEvent_t eFork = nullptr, eJoin = nullptr;
    static bool init_ok = false;
    if (!init_ok) {
        bool ok = (cudaStreamCreateWithFlags(&s1, cudaStreamNonBlocking) == cudaSuccess);
        ok = ok && (cudaEventCreateWithFlags(&eFork, cudaEventDisableTiming) == cudaSuccess);
        ok = ok && (cudaEventCreateWithFlags(&eJoin, cudaEventDisableTiming) == cudaSuccess);
        init_ok = ok;
        if (!ok) s1 = nullptr;
    }

    prep_kernel<<<PREP_BLOCKS, 256>>>(x, Wq, Wk, Wv, Wo, xh, wh);

    const dim3 gQKV(3 * D_MODEL / 128, SEQ / 128);   // (24, 16) per batch
    const dim3 gAttn(SEQ / 256, NHEAD);              // (8, 16) per batch
    const dim3 gOut(D_MODEL / 128, SEQ / 128);       // (8, 16) per batch

    if (s1) {
        // fork: batch 1 stream waits on prep
        cudaEventRecord(eFork, 0);
        cudaStreamWaitEvent(s1, eFork, 0);

        // batch 0 on capture (default) stream
        gemm_qkv<<<gQKV, 256, GEMM_SMEM>>>(xh, wh, bq, bk, bv, qh, kh, vh, 0);
        attn_mma<<<gAttn, 256, ATTN_SMEM>>>(qh, kh, vh, oh, 0);
        gemm_out<<<gOut, 256, GEMM_SMEM>>>(oh, wh + (size_t)3 * WN, bo, out, 0);

        // batch 1 on side stream
        gemm_qkv<<<gQKV, 256, GEMM_SMEM, s1>>>(xh, wh, bq, bk, bv, qh, kh, vh, SEQ);
        attn_mma<<<gAttn, 256, ATTN_SMEM, s1>>>(qh, kh, vh, oh, 1);
        gemm_out<<<gOut, 256, GEMM_SMEM, s1>>>(oh, wh + (size_t)3 * WN, bo, out, SEQ);

        // join
        cudaEventRecord(eJoin, s1);
        cudaStreamWaitEvent(0, eJoin, 0);
    } else {
        // fallback: serial on default stream
        gemm_qkv<<<gQKV, 256, GEMM_SMEM>>>(xh, wh, bq, bk, bv, qh, kh, vh, 0);
        gemm_qkv<<<gQKV, 256, GEMM_SMEM>>>(xh, wh, bq, bk, bv, qh, kh, vh, SEQ);
        attn_mma<<<gAttn, 256, ATTN_SMEM>>>(qh, kh, vh, oh, 0);
        attn_mma<<<gAttn, 256, ATTN_SMEM>>>(qh, kh, vh, oh, 1);
        gemm_out<<<gOut, 256, GEMM_SMEM>>>(oh, wh + (size_t)3 * WN, bo, out, 0);
        gemm_out<<<gOut, 256, GEMM_SMEM>>>(oh, wh + (size_t)3 * WN, bo, out, SEQ);
    }
}